// round 2
// baseline (speedup 1.0000x reference)
#include <cuda_runtime.h>
#include <cuda_bf16.h>
#include <math.h>

#define DIM 256
#define BB  4
#define TT  4096
#define ROWS (BB*TT)          // 16384

// ---------------- scratch (device globals; no allocation allowed) ----------
__device__ float g_xn  [ROWS*DIM];
__device__ float g_q   [ROWS*DIM];
__device__ float g_k   [ROWS*DIM];
__device__ float g_v   [ROWS*DIM];
__device__ float g_attn[ROWS*DIM];
__device__ float g_x2  [ROWS*DIM];
__device__ float g_hn  [ROWS*DIM];
__device__ float g_h   [ROWS*4*DIM];

// ---------------- RMSNorm: one row (256 elems) per 256-thread block --------
__global__ void rmsnorm_kernel(const float* __restrict__ x,
                               const float* __restrict__ w,
                               float* __restrict__ out)
{
    int row = blockIdx.x;
    int t   = threadIdx.x;
    float v = x[(size_t)row*DIM + t];
    float s = v*v;
    #pragma unroll
    for (int o = 16; o; o >>= 1) s += __shfl_xor_sync(0xffffffffu, s, o);
    __shared__ float ws[8];
    if ((t & 31) == 0) ws[t >> 5] = s;
    __syncthreads();
    float tot = ws[0]+ws[1]+ws[2]+ws[3]+ws[4]+ws[5]+ws[6]+ws[7];
    float inv = rsqrtf(tot * (1.0f/DIM) + 1e-6f);
    out[(size_t)row*DIM + t] = v * inv * w[t];
}

// ---------------- generic fp32 GEMM: C = epi(A @ W^T + bias [+ R]) ---------
// A [M,K] row-major, W [N,K] row-major. Tiles 128x128x16, 256 threads, 8x8.
#define GBM 128
#define GBN 128
#define GBK 16

enum { EPI_NONE = 0, EPI_RES = 1, EPI_GELU = 2 };

template<int EPI>
__global__ void __launch_bounds__(256)
gemm_kernel(const float* __restrict__ A, const float* __restrict__ W,
            const float* __restrict__ bias, const float* __restrict__ R,
            float* __restrict__ C, int M, int N, int K)
{
    __shared__ float As[GBK][GBM+4];
    __shared__ float Bs[GBK][GBN+4];

    const int mBase = blockIdx.y * GBM;
    const int nBase = blockIdx.x * GBN;
    const int tid = threadIdx.x;
    const int tx = tid & 15;     // n dim
    const int ty = tid >> 4;     // m dim

    float acc[8][8];
    #pragma unroll
    for (int i = 0; i < 8; i++)
        #pragma unroll
        for (int j = 0; j < 8; j++) acc[i][j] = 0.f;

    for (int kt = 0; kt < K; kt += GBK) {
        // load A tile (128x16) and W tile (128x16), transposed into smem
        #pragma unroll
        for (int i = 0; i < 2; i++) {
            int f  = tid + i*256;          // 0..511
            int m  = f >> 2;               // 0..127
            int k4 = (f & 3) << 2;         // 0,4,8,12
            float4 av = *(const float4*)&A[(size_t)(mBase+m)*K + kt + k4];
            As[k4+0][m] = av.x; As[k4+1][m] = av.y;
            As[k4+2][m] = av.z; As[k4+3][m] = av.w;
            float4 wv = *(const float4*)&W[(size_t)(nBase+m)*K + kt + k4];
            Bs[k4+0][m] = wv.x; Bs[k4+1][m] = wv.y;
            Bs[k4+2][m] = wv.z; Bs[k4+3][m] = wv.w;
        }
        __syncthreads();

        #pragma unroll
        for (int k = 0; k < GBK; k++) {
            float a[8], b[8];
            *(float4*)&a[0] = *(const float4*)&As[k][ty*8];
            *(float4*)&a[4] = *(const float4*)&As[k][ty*8+4];
            *(float4*)&b[0] = *(const float4*)&Bs[k][tx*8];
            *(float4*)&b[4] = *(const float4*)&Bs[k][tx*8+4];
            #pragma unroll
            for (int i = 0; i < 8; i++)
                #pragma unroll
                for (int j = 0; j < 8; j++)
                    acc[i][j] += a[i]*b[j];
        }
        __syncthreads();
    }

    // epilogue
    float bb[8];
    #pragma unroll
    for (int j = 0; j < 8; j++) bb[j] = bias[nBase + tx*8 + j];

    #pragma unroll
    for (int i = 0; i < 8; i++) {
        size_t off = (size_t)(mBase + ty*8 + i) * N + nBase + tx*8;
        float o[8];
        #pragma unroll
        for (int j = 0; j < 8; j++) {
            float c = acc[i][j] + bb[j];
            if (EPI == EPI_GELU)
                c = 0.5f * c * (1.0f + erff(c * 0.70710678118654752f));
            o[j] = c;
        }
        if (EPI == EPI_RES) {
            float4 r0 = *(const float4*)&R[off];
            float4 r1 = *(const float4*)&R[off+4];
            o[0]+=r0.x; o[1]+=r0.y; o[2]+=r0.z; o[3]+=r0.w;
            o[4]+=r1.x; o[5]+=r1.y; o[6]+=r1.z; o[7]+=r1.w;
        }
        *(float4*)&C[off]   = make_float4(o[0],o[1],o[2],o[3]);
        *(float4*)&C[off+4] = make_float4(o[4],o[5],o[6],o[7]);
    }
}

// ---------------- flash attention (fp32, causal, d=256) --------------------
#define FBM 64
#define FBN 64
#define FDP 260                  // 256 + 4 pad (kills K-row bank conflicts)
#define PSTRIDE 68
#define FLASH_SMEM_BYTES ((3*FBM*FDP + FBM*PSTRIDE) * 4)   // 217088

__global__ void __launch_bounds__(256, 1)
flash_kernel(const float* __restrict__ Q, const float* __restrict__ K,
             const float* __restrict__ V, float* __restrict__ O)
{
    extern __shared__ float sm[];
    float* Qs = sm;                        // [64][260]
    float* Ks = Qs + FBM*FDP;              // [64][260]
    float* Vs = Ks + FBN*FDP;              // [64][260]
    float* Ps = Vs + FBN*FDP;              // [64][68]

    const int qi  = gridDim.x - 1 - blockIdx.x;   // heavy tiles first
    const int b   = blockIdx.y;
    const int tid = threadIdx.x;
    const int tx  = tid & 15;   // n / dcol dim
    const int ty  = tid >> 4;   // m dim

    const float scale = 0.0625f;  // 1/sqrt(256)
    const float* Qg = Q + ((size_t)b*TT + (size_t)qi*FBM) * DIM;

    // load Q tile, pre-scaled
    #pragma unroll
    for (int i = 0; i < 16; i++) {
        int f  = tid + i*256;
        int r  = f >> 6;
        int c4 = (f & 63) << 2;
        float4 qv = *(const float4*)(Qg + (size_t)r*DIM + c4);
        float* d = Qs + r*FDP + c4;
        d[0]=qv.x*scale; d[1]=qv.y*scale; d[2]=qv.z*scale; d[3]=qv.w*scale;
    }

    float Oc[4][16];
    #pragma unroll
    for (int i = 0; i < 4; i++)
        #pragma unroll
        for (int j = 0; j < 16; j++) Oc[i][j] = 0.f;
    float mrow[4] = {-1e30f,-1e30f,-1e30f,-1e30f};
    float lrow[4] = {0.f,0.f,0.f,0.f};

    for (int kj = 0; kj <= qi; kj++) {
        const float* Kg = K + ((size_t)b*TT + (size_t)kj*FBN) * DIM;
        const float* Vg = V + ((size_t)b*TT + (size_t)kj*FBN) * DIM;

        __syncthreads();   // protect Ks/Vs/Ps from previous iteration readers
        #pragma unroll
        for (int i = 0; i < 16; i++) {
            int f  = tid + i*256;
            int r  = f >> 6;
            int c4 = (f & 63) << 2;
            *(float4*)(Ks + r*FDP + c4) = *(const float4*)(Kg + (size_t)r*DIM + c4);
            *(float4*)(Vs + r*FDP + c4) = *(const float4*)(Vg + (size_t)r*DIM + c4);
        }
        __syncthreads();

        // S = Qs * Ks^T  (4x4 per thread)
        float S[4][4];
        #pragma unroll
        for (int i = 0; i < 4; i++)
            #pragma unroll
            for (int j = 0; j < 4; j++) S[i][j] = 0.f;

        #pragma unroll 8
        for (int d = 0; d < DIM; d += 4) {
            float4 qv[4], kv[4];
            #pragma unroll
            for (int i = 0; i < 4; i++)
                qv[i] = *(const float4*)(Qs + (ty*4+i)*FDP + d);
            #pragma unroll
            for (int j = 0; j < 4; j++)
                kv[j] = *(const float4*)(Ks + (tx*4+j)*FDP + d);
            #pragma unroll
            for (int i = 0; i < 4; i++)
                #pragma unroll
                for (int j = 0; j < 4; j++) {
                    S[i][j] += qv[i].x*kv[j].x;
                    S[i][j] += qv[i].y*kv[j].y;
                    S[i][j] += qv[i].z*kv[j].z;
                    S[i][j] += qv[i].w*kv[j].w;
                }
        }

        if (kj == qi) {   // causal mask on diagonal tile
            #pragma unroll
            for (int i = 0; i < 4; i++)
                #pragma unroll
                for (int j = 0; j < 4; j++)
                    if (tx*4 + j > ty*4 + i) S[i][j] = -1e30f;
        }

        // online softmax (row stats reduced across the 16 tx lanes)
        #pragma unroll
        for (int i = 0; i < 4; i++) {
            float tm = fmaxf(fmaxf(S[i][0],S[i][1]), fmaxf(S[i][2],S[i][3]));
            #pragma unroll
            for (int o = 8; o; o >>= 1)
                tm = fmaxf(tm, __shfl_xor_sync(0xffffffffu, tm, o, 16));
            float nm = fmaxf(mrow[i], tm);
            float alpha = __expf(mrow[i] - nm);
            float rs = 0.f;
            #pragma unroll
            for (int j = 0; j < 4; j++) {
                S[i][j] = __expf(S[i][j] - nm);
                rs += S[i][j];
            }
            #pragma unroll
            for (int o = 8; o; o >>= 1)
                rs += __shfl_xor_sync(0xffffffffu, rs, o, 16);
            lrow[i] = lrow[i]*alpha + rs;
            mrow[i] = nm;
            #pragma unroll
            for (int j = 0; j < 16; j++) Oc[i][j] *= alpha;
            float* p = Ps + (ty*4+i)*PSTRIDE + tx*4;
            p[0]=S[i][0]; p[1]=S[i][1]; p[2]=S[i][2]; p[3]=S[i][3];
        }
        __syncthreads();

        // O += P @ V
        #pragma unroll 8
        for (int n = 0; n < FBN; n++) {
            float p0 = Ps[(ty*4+0)*PSTRIDE + n];
            float p1 = Ps[(ty*4+1)*PSTRIDE + n];
            float p2 = Ps[(ty*4+2)*PSTRIDE + n];
            float p3 = Ps[(ty*4+3)*PSTRIDE + n];
            const float* vr = Vs + n*FDP + tx*16;
            float4 v0 = *(const float4*)(vr+0);
            float4 v1 = *(const float4*)(vr+4);
            float4 v2 = *(const float4*)(vr+8);
            float4 v3 = *(const float4*)(vr+12);
            float vv[16] = {v0.x,v0.y,v0.z,v0.w, v1.x,v1.y,v1.z,v1.w,
                            v2.x,v2.y,v2.z,v2.w, v3.x,v3.y,v3.z,v3.w};
            #pragma unroll
            for (int j = 0; j < 16; j++) {
                Oc[0][j] += p0*vv[j];
                Oc[1][j] += p1*vv[j];
                Oc[2][j] += p2*vv[j];
                Oc[3][j] += p3*vv[j];
            }
        }
    }

    // write out
    float* Og = O + ((size_t)b*TT + (size_t)qi*FBM) * DIM;
    #pragma unroll
    for (int i = 0; i < 4; i++) {
        float inv = 1.0f / lrow[i];
        float* dst = Og + (size_t)(ty*4+i)*DIM + tx*16;
        #pragma unroll
        for (int j4 = 0; j4 < 4; j4++) {
            float4 ov = make_float4(Oc[i][j4*4+0]*inv, Oc[i][j4*4+1]*inv,
                                    Oc[i][j4*4+2]*inv, Oc[i][j4*4+3]*inv);
            *(float4*)(dst + j4*4) = ov;
        }
    }
}

// ---------------- launch ---------------------------------------------------
extern "C" void kernel_launch(void* const* d_in, const int* in_sizes, int n_in,
                              void* d_out, int out_size)
{
    const float* x           = (const float*)d_in[0];
    const float* attn_norm_w = (const float*)d_in[1];
    const float* mlp_norm_w  = (const float*)d_in[2];
    const float* wq = (const float*)d_in[3];  const float* bq = (const float*)d_in[4];
    const float* wk = (const float*)d_in[5];  const float* bk = (const float*)d_in[6];
    const float* wv = (const float*)d_in[7];  const float* bv = (const float*)d_in[8];
    const float* wo = (const float*)d_in[9];  const float* bo = (const float*)d_in[10];
    const float* w1 = (const float*)d_in[11]; const float* b1 = (const float*)d_in[12];
    const float* w2 = (const float*)d_in[13]; const float* b2 = (const float*)d_in[14];
    float* out = (float*)d_out;

    float *xn, *q, *k, *v, *attn, *x2, *hn, *h;
    cudaGetSymbolAddress((void**)&xn,   g_xn);
    cudaGetSymbolAddress((void**)&q,    g_q);
    cudaGetSymbolAddress((void**)&k,    g_k);
    cudaGetSymbolAddress((void**)&v,    g_v);
    cudaGetSymbolAddress((void**)&attn, g_attn);
    cudaGetSymbolAddress((void**)&x2,   g_x2);
    cudaGetSymbolAddress((void**)&hn,   g_hn);
    cudaGetSymbolAddress((void**)&h,    g_h);

    cudaFuncSetAttribute(flash_kernel,
                         cudaFuncAttributeMaxDynamicSharedMemorySize,
                         FLASH_SMEM_BYTES);

    // 1. attention-branch RMSNorm
    rmsnorm_kernel<<<ROWS, 256>>>(x, attn_norm_w, xn);

    // 2. QKV projections
    dim3 g256(DIM/GBN, ROWS/GBM);   // (2,128)
    gemm_kernel<EPI_NONE><<<g256, 256>>>(xn, wq, bq, nullptr, q, ROWS, DIM, DIM);
    gemm_kernel<EPI_NONE><<<g256, 256>>>(xn, wk, bk, nullptr, k, ROWS, DIM, DIM);
    gemm_kernel<EPI_NONE><<<g256, 256>>>(xn, wv, bv, nullptr, v, ROWS, DIM, DIM);

    // 3. causal attention
    flash_kernel<<<dim3(TT/FBM, BB), 256, FLASH_SMEM_BYTES>>>(q, k, v, attn);

    // 4. output projection + residual
    gemm_kernel<EPI_RES><<<g256, 256>>>(attn, wo, bo, x, x2, ROWS, DIM, DIM);

    // 5. MLP-branch RMSNorm
    rmsnorm_kernel<<<ROWS, 256>>>(x2, mlp_norm_w, hn);

    // 6. MLP up + GELU
    dim3 g1024(4*DIM/GBN, ROWS/GBM);  // (8,128)
    gemm_kernel<EPI_GELU><<<g1024, 256>>>(hn, w1, b1, nullptr, h, ROWS, 4*DIM, DIM);

    // 7. MLP down + residual -> out
    gemm_kernel<EPI_RES><<<g256, 256>>>(h, w2, b2, x2, out, ROWS, DIM, 4*DIM);
}

// round 5
// speedup vs baseline: 3.1936x; 3.1936x over previous
#include <cuda_runtime.h>
#include <cuda_bf16.h>
#include <math.h>
#include <cstdint>

#define DIM 256
#define BB  4
#define TT  4096
#define ROWS (BB*TT)          // 16384

// ---------------- scratch (device globals; no allocation allowed) ----------
__device__ float g_xn  [ROWS*DIM];
__device__ float g_q   [ROWS*DIM];
__device__ float g_k   [ROWS*DIM];
__device__ float g_v   [ROWS*DIM];
__device__ float g_attn[ROWS*DIM];
__device__ float g_x2  [ROWS*DIM];
__device__ float g_hn  [ROWS*DIM];
__device__ float g_h   [ROWS*4*DIM];

// ---------------- helpers ---------------------------------------------------
__device__ __forceinline__ float f2tf32(float x) {
    uint32_t u = __float_as_uint(x);
    asm("cvt.rna.tf32.f32 %0, %0;" : "+r"(u));
    return __uint_as_float(u);
}
__device__ __forceinline__ void mma8(float* c,
                                     uint32_t a0, uint32_t a1, uint32_t a2, uint32_t a3,
                                     uint32_t b0, uint32_t b1) {
    asm volatile(
        "mma.sync.aligned.m16n8k8.row.col.f32.tf32.tf32.f32 "
        "{%0,%1,%2,%3}, {%4,%5,%6,%7}, {%8,%9}, {%0,%1,%2,%3};"
        : "+f"(c[0]), "+f"(c[1]), "+f"(c[2]), "+f"(c[3])
        : "r"(a0), "r"(a1), "r"(a2), "r"(a3), "r"(b0), "r"(b1));
}

// ---------------- RMSNorm ---------------------------------------------------
__global__ void rmsnorm_kernel(const float* __restrict__ x,
                               const float* __restrict__ w,
                               float* __restrict__ out)
{
    int row = blockIdx.x;
    int t   = threadIdx.x;
    float v = x[(size_t)row*DIM + t];
    float s = v*v;
    #pragma unroll
    for (int o = 16; o; o >>= 1) s += __shfl_xor_sync(0xffffffffu, s, o);
    __shared__ float ws[8];
    if ((t & 31) == 0) ws[t >> 5] = s;
    __syncthreads();
    float tot = ws[0]+ws[1]+ws[2]+ws[3]+ws[4]+ws[5]+ws[6]+ws[7];
    float inv = rsqrtf(tot * (1.0f/DIM) + 1e-6f);
    out[(size_t)row*DIM + t] = v * inv * w[t];
}

// ---------------- SIMT fp32 GEMM (verified R2): C = epi(A@W^T + b [+R]) ----
#define GBM 128
#define GBN 128
#define GBK 16

enum { EPI_NONE = 0, EPI_RES = 1, EPI_GELU = 2 };

template<int EPI>
__global__ void __launch_bounds__(256)
gemm_kernel(const float* __restrict__ A, const float* __restrict__ W,
            const float* __restrict__ bias, const float* __restrict__ R,
            float* __restrict__ C, int M, int N, int K)
{
    __shared__ float As[GBK][GBM+4];
    __shared__ float Bs[GBK][GBN+4];

    const int mBase = blockIdx.y * GBM;
    const int nBase = blockIdx.x * GBN;
    const int tid = threadIdx.x;
    const int tx = tid & 15;
    const int ty = tid >> 4;

    float acc[8][8];
    #pragma unroll
    for (int i = 0; i < 8; i++)
        #pragma unroll
        for (int j = 0; j < 8; j++) acc[i][j] = 0.f;

    for (int kt = 0; kt < K; kt += GBK) {
        #pragma unroll
        for (int i = 0; i < 2; i++) {
            int f  = tid + i*256;
            int m  = f >> 2;
            int k4 = (f & 3) << 2;
            float4 av = *(const float4*)&A[(size_t)(mBase+m)*K + kt + k4];
            As[k4+0][m] = av.x; As[k4+1][m] = av.y;
            As[k4+2][m] = av.z; As[k4+3][m] = av.w;
            float4 wv = *(const float4*)&W[(size_t)(nBase+m)*K + kt + k4];
            Bs[k4+0][m] = wv.x; Bs[k4+1][m] = wv.y;
            Bs[k4+2][m] = wv.z; Bs[k4+3][m] = wv.w;
        }
        __syncthreads();

        #pragma unroll
        for (int k = 0; k < GBK; k++) {
            float a[8], b[8];
            *(float4*)&a[0] = *(const float4*)&As[k][ty*8];
            *(float4*)&a[4] = *(const float4*)&As[k][ty*8+4];
            *(float4*)&b[0] = *(const float4*)&Bs[k][tx*8];
            *(float4*)&b[4] = *(const float4*)&Bs[k][tx*8+4];
            #pragma unroll
            for (int i = 0; i < 8; i++)
                #pragma unroll
                for (int j = 0; j < 8; j++)
                    acc[i][j] += a[i]*b[j];
        }
        __syncthreads();
    }

    float bb[8];
    #pragma unroll
    for (int j = 0; j < 8; j++) bb[j] = bias[nBase + tx*8 + j];

    #pragma unroll
    for (int i = 0; i < 8; i++) {
        size_t off = (size_t)(mBase + ty*8 + i) * N + nBase + tx*8;
        float o[8];
        #pragma unroll
        for (int j = 0; j < 8; j++) {
            float c = acc[i][j] + bb[j];
            if (EPI == EPI_GELU)
                c = 0.5f * c * (1.0f + erff(c * 0.70710678118654752f));
            o[j] = c;
        }
        if (EPI == EPI_RES) {
            float4 r0 = *(const float4*)&R[off];
            float4 r1 = *(const float4*)&R[off+4];
            o[0]+=r0.x; o[1]+=r0.y; o[2]+=r0.z; o[3]+=r0.w;
            o[4]+=r1.x; o[5]+=r1.y; o[6]+=r1.z; o[7]+=r1.w;
        }
        *(float4*)&C[off]   = make_float4(o[0],o[1],o[2],o[3]);
        *(float4*)&C[off+4] = make_float4(o[4],o[5],o[6],o[7]);
    }
}

// ---------------- flash attention: mma.sync tf32, causal, d=256 ------------
// 64x64 tiles, 8 warps = 4(m) x 2(n). Pads: Qs/Ks 260 (bank 4g+t), Vs 264 (8t+g).
#define FBM 64
#define FBN 64
#define QP 260
#define KP 260
#define VP 264
#define PST 68
// floats: Qs 64*260 + Ks 64*260 + Vs 64*264 + Ps 64*68 + stats 256
#define FLASH_SMEM_BYTES ((64*QP + 64*KP + 64*VP + 64*PST + 256) * 4)  // 219136

__global__ void __launch_bounds__(256, 1)
flash_mma_kernel(const float* __restrict__ Q, const float* __restrict__ K,
                 const float* __restrict__ V, float* __restrict__ O)
{
    extern __shared__ float sm[];
    float* Qs   = sm;
    float* Ks   = Qs + 64*QP;
    float* Vs   = Ks + 64*KP;
    float* Ps   = Vs + 64*VP;
    float* pmax = Ps + 64*PST;     // [2][64]
    float* psum = pmax + 128;      // [2][64]

    const int qi  = gridDim.x - 1 - blockIdx.x;   // heavy tiles first
    const int b   = blockIdx.y;
    const int tid = threadIdx.x;
    const int wid = tid >> 5;
    const int lane = tid & 31;
    const int wm = wid & 3;        // m-warp: rows wm*16
    const int wn = wid >> 2;       // n-warp: S cols wn*32, O cols wn*128
    const int g  = lane >> 2;      // group id (row within tile)
    const int t  = lane & 3;       // thread in group

    const float scale = 0.0625f;   // 1/sqrt(256)
    const float* Qg = Q + ((size_t)b*TT + (size_t)qi*FBM) * DIM;

    // load Q tile, pre-scaled, tf32-rounded
    #pragma unroll
    for (int i = 0; i < 16; i++) {
        int f  = tid + i*256;
        int r  = f >> 6;
        int c4 = (f & 63) << 2;
        float4 qv = *(const float4*)(Qg + (size_t)r*DIM + c4);
        *(float4*)(Qs + r*QP + c4) = make_float4(
            f2tf32(qv.x*scale), f2tf32(qv.y*scale),
            f2tf32(qv.z*scale), f2tf32(qv.w*scale));
    }

    float o[16][4];
    #pragma unroll
    for (int i = 0; i < 16; i++)
        #pragma unroll
        for (int j = 0; j < 4; j++) o[i][j] = 0.f;
    float m0 = -1e30f, m1 = -1e30f, l0 = 0.f, l1 = 0.f;

    const int row0 = wm*16 + g;          // local S/O row of c0,c1
    const float* QA = Qs + row0*QP;      // a-frag base (row0; row0+8 = +8*QP)

    for (int kj = 0; kj <= qi; kj++) {
        const float* Kg = K + ((size_t)b*TT + (size_t)kj*FBN) * DIM;
        const float* Vg = V + ((size_t)b*TT + (size_t)kj*FBN) * DIM;

        __syncthreads();   // previous PV done before overwriting Ks/Vs
        #pragma unroll
        for (int i = 0; i < 16; i++) {
            int f  = tid + i*256;
            int r  = f >> 6;
            int c4 = (f & 63) << 2;
            float4 kv = *(const float4*)(Kg + (size_t)r*DIM + c4);
            *(float4*)(Ks + r*KP + c4) = make_float4(
                f2tf32(kv.x), f2tf32(kv.y), f2tf32(kv.z), f2tf32(kv.w));
            float4 vv = *(const float4*)(Vg + (size_t)r*DIM + c4);
            *(float4*)(Vs + r*VP + c4) = make_float4(
                f2tf32(vv.x), f2tf32(vv.y), f2tf32(vv.z), f2tf32(vv.w));
        }
        __syncthreads();

        // ---- S = Q K^T on tensor cores --------------------------------
        float s[4][4];
        #pragma unroll
        for (int nt = 0; nt < 4; nt++)
            #pragma unroll
            for (int j = 0; j < 4; j++) s[nt][j] = 0.f;

        #pragma unroll 4
        for (int k8 = 0; k8 < 32; k8++) {
            const int k0 = k8*8 + t;
            uint32_t a0 = __float_as_uint(QA[k0]);
            uint32_t a1 = __float_as_uint(QA[8*QP + k0]);
            uint32_t a2 = __float_as_uint(QA[k0 + 4]);
            uint32_t a3 = __float_as_uint(QA[8*QP + k0 + 4]);
            #pragma unroll
            for (int nt = 0; nt < 4; nt++) {
                const float* KB = Ks + (wn*32 + nt*8 + g)*KP + k0;
                uint32_t b0 = __float_as_uint(KB[0]);
                uint32_t b1 = __float_as_uint(KB[4]);
                mma8(s[nt], a0, a1, a2, a3, b0, b1);
            }
        }

        // causal mask on diagonal tile (local coords suffice: kj==qi)
        if (kj == qi) {
            #pragma unroll
            for (int nt = 0; nt < 4; nt++) {
                int col = wn*32 + nt*8 + 2*t;
                if (col     > row0)     s[nt][0] = -1e30f;
                if (col + 1 > row0)     s[nt][1] = -1e30f;
                if (col     > row0 + 8) s[nt][2] = -1e30f;
                if (col + 1 > row0 + 8) s[nt][3] = -1e30f;
            }
        }

        // ---- partial row max -> smem ----------------------------------
        float pm0 = -1e30f, pm1 = -1e30f;
        #pragma unroll
        for (int nt = 0; nt < 4; nt++) {
            pm0 = fmaxf(pm0, fmaxf(s[nt][0], s[nt][1]));
            pm1 = fmaxf(pm1, fmaxf(s[nt][2], s[nt][3]));
        }
        pm0 = fmaxf(pm0, __shfl_xor_sync(0xffffffffu, pm0, 1));
        pm0 = fmaxf(pm0, __shfl_xor_sync(0xffffffffu, pm0, 2));
        pm1 = fmaxf(pm1, __shfl_xor_sync(0xffffffffu, pm1, 1));
        pm1 = fmaxf(pm1, __shfl_xor_sync(0xffffffffu, pm1, 2));
        if (t == 0) {
            pmax[wn*64 + row0]     = pm0;
            pmax[wn*64 + row0 + 8] = pm1;
        }
        __syncthreads();

        float nm0 = fmaxf(m0, fmaxf(pmax[row0],     pmax[64 + row0]));
        float nm1 = fmaxf(m1, fmaxf(pmax[row0 + 8], pmax[64 + row0 + 8]));
        float alpha0 = __expf(m0 - nm0);
        float alpha1 = __expf(m1 - nm1);
        m0 = nm0; m1 = nm1;

        // ---- exp, partial sums, stage P to smem ------------------------
        float rs0 = 0.f, rs1 = 0.f;
        #pragma unroll
        for (int nt = 0; nt < 4; nt++) {
            s[nt][0] = __expf(s[nt][0] - nm0);
            s[nt][1] = __expf(s[nt][1] - nm0);
            s[nt][2] = __expf(s[nt][2] - nm1);
            s[nt][3] = __expf(s[nt][3] - nm1);
            rs0 += s[nt][0] + s[nt][1];
            rs1 += s[nt][2] + s[nt][3];
            int col = wn*32 + nt*8 + 2*t;
            *(float2*)(Ps + row0*PST + col) =
                make_float2(f2tf32(s[nt][0]), f2tf32(s[nt][1]));
            *(float2*)(Ps + (row0+8)*PST + col) =
                make_float2(f2tf32(s[nt][2]), f2tf32(s[nt][3]));
        }
        rs0 += __shfl_xor_sync(0xffffffffu, rs0, 1);
        rs0 += __shfl_xor_sync(0xffffffffu, rs0, 2);
        rs1 += __shfl_xor_sync(0xffffffffu, rs1, 1);
        rs1 += __shfl_xor_sync(0xffffffffu, rs1, 2);
        if (t == 0) {
            psum[wn*64 + row0]     = rs0;
            psum[wn*64 + row0 + 8] = rs1;
        }
        __syncthreads();

        l0 = l0*alpha0 + psum[row0]     + psum[64 + row0];
        l1 = l1*alpha1 + psum[row0 + 8] + psum[64 + row0 + 8];

        // rescale O
        #pragma unroll
        for (int nt = 0; nt < 16; nt++) {
            o[nt][0] *= alpha0; o[nt][1] *= alpha0;
            o[nt][2] *= alpha1; o[nt][3] *= alpha1;
        }

        // ---- O += P V on tensor cores ----------------------------------
        const float* PA = Ps + row0*PST;
        #pragma unroll
        for (int k8 = 0; k8 < 8; k8++) {
            const int k0 = k8*8 + t;
            uint32_t a0 = __float_as_uint(PA[k0]);
            uint32_t a1 = __float_as_uint(PA[8*PST + k0]);
            uint32_t a2 = __float_as_uint(PA[k0 + 4]);
            uint32_t a3 = __float_as_uint(PA[8*PST + k0 + 4]);
            #pragma unroll
            for (int nt = 0; nt < 16; nt++) {
                const int nb = wn*128 + nt*8 + g;
                uint32_t b0 = __float_as_uint(Vs[k0*VP + nb]);
                uint32_t b1 = __float_as_uint(Vs[(k0+4)*VP + nb]);
                mma8(o[nt], a0, a1, a2, a3, b0, b1);
            }
        }
    }

    // ---- write out ---------------------------------------------------------
    float inv0 = 1.0f / l0;
    float inv1 = 1.0f / l1;
    float* Og = O + ((size_t)b*TT + (size_t)qi*FBM) * DIM;
    #pragma unroll
    for (int nt = 0; nt < 16; nt++) {
        int col = wn*128 + nt*8 + 2*t;
        *(float2*)(Og + (size_t)row0*DIM + col) =
            make_float2(o[nt][0]*inv0, o[nt][1]*inv0);
        *(float2*)(Og + (size_t)(row0+8)*DIM + col) =
            make_float2(o[nt][2]*inv1, o[nt][3]*inv1);
    }
}

// ---------------- launch ---------------------------------------------------
extern "C" void kernel_launch(void* const* d_in, const int* in_sizes, int n_in,
                              void* d_out, int out_size)
{
    const float* x           = (const float*)d_in[0];
    const float* attn_norm_w = (const float*)d_in[1];
    const float* mlp_norm_w  = (const float*)d_in[2];
    const float* wq = (const float*)d_in[3];  const float* bq = (const float*)d_in[4];
    const float* wk = (const float*)d_in[5];  const float* bk = (const float*)d_in[6];
    const float* wv = (const float*)d_in[7];  const float* bv = (const float*)d_in[8];
    const float* wo = (const float*)d_in[9];  const float* bo = (const float*)d_in[10];
    const float* w1 = (const float*)d_in[11]; const float* b1 = (const float*)d_in[12];
    const float* w2 = (const float*)d_in[13]; const float* b2 = (const float*)d_in[14];
    float* out = (float*)d_out;

    float *xn, *q, *k, *v, *attn, *x2, *hn, *h;
    cudaGetSymbolAddress((void**)&xn,   g_xn);
    cudaGetSymbolAddress((void**)&q,    g_q);
    cudaGetSymbolAddress((void**)&k,    g_k);
    cudaGetSymbolAddress((void**)&v,    g_v);
    cudaGetSymbolAddress((void**)&attn, g_attn);
    cudaGetSymbolAddress((void**)&x2,   g_x2);
    cudaGetSymbolAddress((void**)&hn,   g_hn);
    cudaGetSymbolAddress((void**)&h,    g_h);

    cudaFuncSetAttribute(flash_mma_kernel,
                         cudaFuncAttributeMaxDynamicSharedMemorySize,
                         FLASH_SMEM_BYTES);

    // 1. attention-branch RMSNorm
    rmsnorm_kernel<<<ROWS, 256>>>(x, attn_norm_w, xn);

    // 2. QKV projections (SIMT fp32)
    dim3 g256(DIM/GBN, ROWS/GBM);   // (2,128)
    gemm_kernel<EPI_NONE><<<g256, 256>>>(xn, wq, bq, nullptr, q, ROWS, DIM, DIM);
    gemm_kernel<EPI_NONE><<<g256, 256>>>(xn, wk, bk, nullptr, k, ROWS, DIM, DIM);
    gemm_kernel<EPI_NONE><<<g256, 256>>>(xn, wv, bv, nullptr, v, ROWS, DIM, DIM);

    // 3. causal attention (tensor cores, tf32)
    flash_mma_kernel<<<dim3(TT/FBM, BB), 256, FLASH_SMEM_BYTES>>>(q, k, v, attn);

    // 4. output projection + residual
    gemm_kernel<EPI_RES><<<g256, 256>>>(attn, wo, bo, x, x2, ROWS, DIM, DIM);

    // 5. MLP-branch RMSNorm
    rmsnorm_kernel<<<ROWS, 256>>>(x2, mlp_norm_w, hn);

    // 6. MLP up + GELU
    dim3 g1024(4*DIM/GBN, ROWS/GBM);  // (8,128)
    gemm_kernel<EPI_GELU><<<g1024, 256>>>(hn, w1, b1, nullptr, h, ROWS, 4*DIM, DIM);

    // 7. MLP down + residual -> out
    gemm_kernel<EPI_RES><<<g256, 256>>>(h, w2, b2, x2, out, ROWS, DIM, 4*DIM);
}

// round 6
// speedup vs baseline: 3.1941x; 1.0002x over previous
#include <cuda_runtime.h>
#include <cuda_bf16.h>
#include <math.h>
#include <cstdint>

#define DIM 256
#define BB  4
#define TT  4096
#define ROWS (BB*TT)          // 16384

// ---------------- scratch (device globals; no allocation allowed) ----------
__device__ float g_xn  [ROWS*DIM];
__device__ float g_q   [ROWS*DIM];
__device__ float g_k   [ROWS*DIM];
__device__ float g_v   [ROWS*DIM];
__device__ float g_attn[ROWS*DIM];
__device__ float g_x2  [ROWS*DIM];
__device__ float g_hn  [ROWS*DIM];
__device__ float g_h   [ROWS*4*DIM];

// ---------------- helpers ---------------------------------------------------
__device__ __forceinline__ float f2tf32(float x) {
    uint32_t u = __float_as_uint(x);
    asm("cvt.rna.tf32.f32 %0, %0;" : "+r"(u));
    return __uint_as_float(u);
}
__device__ __forceinline__ void mma8(float* c,
                                     uint32_t a0, uint32_t a1, uint32_t a2, uint32_t a3,
                                     uint32_t b0, uint32_t b1) {
    asm volatile(
        "mma.sync.aligned.m16n8k8.row.col.f32.tf32.tf32.f32 "
        "{%0,%1,%2,%3}, {%4,%5,%6,%7}, {%8,%9}, {%0,%1,%2,%3};"
        : "+f"(c[0]), "+f"(c[1]), "+f"(c[2]), "+f"(c[3])
        : "r"(a0), "r"(a1), "r"(a2), "r"(a3), "r"(b0), "r"(b1));
}

// ---------------- RMSNorm ---------------------------------------------------
__global__ void rmsnorm_kernel(const float* __restrict__ x,
                               const float* __restrict__ w,
                               float* __restrict__ out)
{
    int row = blockIdx.x;
    int t   = threadIdx.x;
    float v = x[(size_t)row*DIM + t];
    float s = v*v;
    #pragma unroll
    for (int o = 16; o; o >>= 1) s += __shfl_xor_sync(0xffffffffu, s, o);
    __shared__ float ws[8];
    if ((t & 31) == 0) ws[t >> 5] = s;
    __syncthreads();
    float tot = ws[0]+ws[1]+ws[2]+ws[3]+ws[4]+ws[5]+ws[6]+ws[7];
    float inv = rsqrtf(tot * (1.0f/DIM) + 1e-6f);
    out[(size_t)row*DIM + t] = v * inv * w[t];
}

// ---------------- SIMT fp32 GEMM (verified R2): C = epi(A@W^T + b [+R]) ----
#define GBM 128
#define GBN 128
#define GBK 16

enum { EPI_NONE = 0, EPI_RES = 1, EPI_GELU = 2 };

template<int EPI>
__global__ void __launch_bounds__(256)
gemm_kernel(const float* __restrict__ A, const float* __restrict__ W,
            const float* __restrict__ bias, const float* __restrict__ R,
            float* __restrict__ C, int M, int N, int K)
{
    __shared__ float As[GBK][GBM+4];
    __shared__ float Bs[GBK][GBN+4];

    const int mBase = blockIdx.y * GBM;
    const int nBase = blockIdx.x * GBN;
    const int tid = threadIdx.x;
    const int tx = tid & 15;
    const int ty = tid >> 4;

    float acc[8][8];
    #pragma unroll
    for (int i = 0; i < 8; i++)
        #pragma unroll
        for (int j = 0; j < 8; j++) acc[i][j] = 0.f;

    for (int kt = 0; kt < K; kt += GBK) {
        #pragma unroll
        for (int i = 0; i < 2; i++) {
            int f  = tid + i*256;
            int m  = f >> 2;
            int k4 = (f & 3) << 2;
            float4 av = *(const float4*)&A[(size_t)(mBase+m)*K + kt + k4];
            As[k4+0][m] = av.x; As[k4+1][m] = av.y;
            As[k4+2][m] = av.z; As[k4+3][m] = av.w;
            float4 wv = *(const float4*)&W[(size_t)(nBase+m)*K + kt + k4];
            Bs[k4+0][m] = wv.x; Bs[k4+1][m] = wv.y;
            Bs[k4+2][m] = wv.z; Bs[k4+3][m] = wv.w;
        }
        __syncthreads();

        #pragma unroll
        for (int k = 0; k < GBK; k++) {
            float a[8], b[8];
            *(float4*)&a[0] = *(const float4*)&As[k][ty*8];
            *(float4*)&a[4] = *(const float4*)&As[k][ty*8+4];
            *(float4*)&b[0] = *(const float4*)&Bs[k][tx*8];
            *(float4*)&b[4] = *(const float4*)&Bs[k][tx*8+4];
            #pragma unroll
            for (int i = 0; i < 8; i++)
                #pragma unroll
                for (int j = 0; j < 8; j++)
                    acc[i][j] += a[i]*b[j];
        }
        __syncthreads();
    }

    float bb[8];
    #pragma unroll
    for (int j = 0; j < 8; j++) bb[j] = bias[nBase + tx*8 + j];

    #pragma unroll
    for (int i = 0; i < 8; i++) {
        size_t off = (size_t)(mBase + ty*8 + i) * N + nBase + tx*8;
        float o[8];
        #pragma unroll
        for (int j = 0; j < 8; j++) {
            float c = acc[i][j] + bb[j];
            if (EPI == EPI_GELU)
                c = 0.5f * c * (1.0f + erff(c * 0.70710678118654752f));
            o[j] = c;
        }
        if (EPI == EPI_RES) {
            float4 r0 = *(const float4*)&R[off];
            float4 r1 = *(const float4*)&R[off+4];
            o[0]+=r0.x; o[1]+=r0.y; o[2]+=r0.z; o[3]+=r0.w;
            o[4]+=r1.x; o[5]+=r1.y; o[6]+=r1.z; o[7]+=r1.w;
        }
        *(float4*)&C[off]   = make_float4(o[0],o[1],o[2],o[3]);
        *(float4*)&C[off+4] = make_float4(o[4],o[5],o[6],o[7]);
    }
}

// ---------------- flash attention: mma.sync tf32, causal, d=256 ------------
// 64x64 tiles, 8 warps = 4(m) x 2(n). Pads: Qs/Ks 260 (bank 4g+t), Vs 264 (8t+g).
#define FBM 64
#define FBN 64
#define QP 260
#define KP 260
#define VP 264
#define PST 68
// floats: Qs 64*260 + Ks 64*260 + Vs 64*264 + Ps 64*68 + stats 256
#define FLASH_SMEM_BYTES ((64*QP + 64*KP + 64*VP + 64*PST + 256) * 4)  // 219136

__global__ void __launch_bounds__(256, 1)
flash_mma_kernel(const float* __restrict__ Q, const float* __restrict__ K,
                 const float* __restrict__ V, float* __restrict__ O)
{
    extern __shared__ float sm[];
    float* Qs   = sm;
    float* Ks   = Qs + 64*QP;
    float* Vs   = Ks + 64*KP;
    float* Ps   = Vs + 64*VP;
    float* pmax = Ps + 64*PST;     // [2][64]
    float* psum = pmax + 128;      // [2][64]

    const int qi  = gridDim.x - 1 - blockIdx.x;   // heavy tiles first
    const int b   = blockIdx.y;
    const int tid = threadIdx.x;
    const int wid = tid >> 5;
    const int lane = tid & 31;
    const int wm = wid & 3;        // m-warp: rows wm*16
    const int wn = wid >> 2;       // n-warp: S cols wn*32, O cols wn*128
    const int g  = lane >> 2;      // group id (row within tile)
    const int t  = lane & 3;       // thread in group

    const float scale = 0.0625f;   // 1/sqrt(256)
    const float* Qg = Q + ((size_t)b*TT + (size_t)qi*FBM) * DIM;

    // load Q tile, pre-scaled, tf32-rounded
    #pragma unroll
    for (int i = 0; i < 16; i++) {
        int f  = tid + i*256;
        int r  = f >> 6;
        int c4 = (f & 63) << 2;
        float4 qv = *(const float4*)(Qg + (size_t)r*DIM + c4);
        *(float4*)(Qs + r*QP + c4) = make_float4(
            f2tf32(qv.x*scale), f2tf32(qv.y*scale),
            f2tf32(qv.z*scale), f2tf32(qv.w*scale));
    }

    float o[16][4];
    #pragma unroll
    for (int i = 0; i < 16; i++)
        #pragma unroll
        for (int j = 0; j < 4; j++) o[i][j] = 0.f;
    float m0 = -1e30f, m1 = -1e30f, l0 = 0.f, l1 = 0.f;

    const int row0 = wm*16 + g;          // local S/O row of c0,c1
    const float* QA = Qs + row0*QP;      // a-frag base (row0; row0+8 = +8*QP)

    for (int kj = 0; kj <= qi; kj++) {
        const float* Kg = K + ((size_t)b*TT + (size_t)kj*FBN) * DIM;
        const float* Vg = V + ((size_t)b*TT + (size_t)kj*FBN) * DIM;

        __syncthreads();   // previous PV done before overwriting Ks/Vs
        #pragma unroll
        for (int i = 0; i < 16; i++) {
            int f  = tid + i*256;
            int r  = f >> 6;
            int c4 = (f & 63) << 2;
            float4 kv = *(const float4*)(Kg + (size_t)r*DIM + c4);
            *(float4*)(Ks + r*KP + c4) = make_float4(
                f2tf32(kv.x), f2tf32(kv.y), f2tf32(kv.z), f2tf32(kv.w));
            float4 vv = *(const float4*)(Vg + (size_t)r*DIM + c4);
            *(float4*)(Vs + r*VP + c4) = make_float4(
                f2tf32(vv.x), f2tf32(vv.y), f2tf32(vv.z), f2tf32(vv.w));
        }
        __syncthreads();

        // ---- S = Q K^T on tensor cores --------------------------------
        float s[4][4];
        #pragma unroll
        for (int nt = 0; nt < 4; nt++)
            #pragma unroll
            for (int j = 0; j < 4; j++) s[nt][j] = 0.f;

        #pragma unroll 4
        for (int k8 = 0; k8 < 32; k8++) {
            const int k0 = k8*8 + t;
            uint32_t a0 = __float_as_uint(QA[k0]);
            uint32_t a1 = __float_as_uint(QA[8*QP + k0]);
            uint32_t a2 = __float_as_uint(QA[k0 + 4]);
            uint32_t a3 = __float_as_uint(QA[8*QP + k0 + 4]);
            #pragma unroll
            for (int nt = 0; nt < 4; nt++) {
                const float* KB = Ks + (wn*32 + nt*8 + g)*KP + k0;
                uint32_t b0 = __float_as_uint(KB[0]);
                uint32_t b1 = __float_as_uint(KB[4]);
                mma8(s[nt], a0, a1, a2, a3, b0, b1);
            }
        }

        // causal mask on diagonal tile (local coords suffice: kj==qi)
        if (kj == qi) {
            #pragma unroll
            for (int nt = 0; nt < 4; nt++) {
                int col = wn*32 + nt*8 + 2*t;
                if (col     > row0)     s[nt][0] = -1e30f;
                if (col + 1 > row0)     s[nt][1] = -1e30f;
                if (col     > row0 + 8) s[nt][2] = -1e30f;
                if (col + 1 > row0 + 8) s[nt][3] = -1e30f;
            }
        }

        // ---- partial row max -> smem ----------------------------------
        float pm0 = -1e30f, pm1 = -1e30f;
        #pragma unroll
        for (int nt = 0; nt < 4; nt++) {
            pm0 = fmaxf(pm0, fmaxf(s[nt][0], s[nt][1]));
            pm1 = fmaxf(pm1, fmaxf(s[nt][2], s[nt][3]));
        }
        pm0 = fmaxf(pm0, __shfl_xor_sync(0xffffffffu, pm0, 1));
        pm0 = fmaxf(pm0, __shfl_xor_sync(0xffffffffu, pm0, 2));
        pm1 = fmaxf(pm1, __shfl_xor_sync(0xffffffffu, pm1, 1));
        pm1 = fmaxf(pm1, __shfl_xor_sync(0xffffffffu, pm1, 2));
        if (t == 0) {
            pmax[wn*64 + row0]     = pm0;
            pmax[wn*64 + row0 + 8] = pm1;
        }
        __syncthreads();

        float nm0 = fmaxf(m0, fmaxf(pmax[row0],     pmax[64 + row0]));
        float nm1 = fmaxf(m1, fmaxf(pmax[row0 + 8], pmax[64 + row0 + 8]));
        float alpha0 = __expf(m0 - nm0);
        float alpha1 = __expf(m1 - nm1);
        m0 = nm0; m1 = nm1;

        // ---- exp, partial sums, stage P to smem ------------------------
        float rs0 = 0.f, rs1 = 0.f;
        #pragma unroll
        for (int nt = 0; nt < 4; nt++) {
            s[nt][0] = __expf(s[nt][0] - nm0);
            s[nt][1] = __expf(s[nt][1] - nm0);
            s[nt][2] = __expf(s[nt][2] - nm1);
            s[nt][3] = __expf(s[nt][3] - nm1);
            rs0 += s[nt][0] + s[nt][1];
            rs1 += s[nt][2] + s[nt][3];
            int col = wn*32 + nt*8 + 2*t;
            *(float2*)(Ps + row0*PST + col) =
                make_float2(f2tf32(s[nt][0]), f2tf32(s[nt][1]));
            *(float2*)(Ps + (row0+8)*PST + col) =
                make_float2(f2tf32(s[nt][2]), f2tf32(s[nt][3]));
        }
        rs0 += __shfl_xor_sync(0xffffffffu, rs0, 1);
        rs0 += __shfl_xor_sync(0xffffffffu, rs0, 2);
        rs1 += __shfl_xor_sync(0xffffffffu, rs1, 1);
        rs1 += __shfl_xor_sync(0xffffffffu, rs1, 2);
        if (t == 0) {
            psum[wn*64 + row0]     = rs0;
            psum[wn*64 + row0 + 8] = rs1;
        }
        __syncthreads();

        l0 = l0*alpha0 + psum[row0]     + psum[64 + row0];
        l1 = l1*alpha1 + psum[row0 + 8] + psum[64 + row0 + 8];

        // rescale O
        #pragma unroll
        for (int nt = 0; nt < 16; nt++) {
            o[nt][0] *= alpha0; o[nt][1] *= alpha0;
            o[nt][2] *= alpha1; o[nt][3] *= alpha1;
        }

        // ---- O += P V on tensor cores ----------------------------------
        const float* PA = Ps + row0*PST;
        #pragma unroll
        for (int k8 = 0; k8 < 8; k8++) {
            const int k0 = k8*8 + t;
            uint32_t a0 = __float_as_uint(PA[k0]);
            uint32_t a1 = __float_as_uint(PA[8*PST + k0]);
            uint32_t a2 = __float_as_uint(PA[k0 + 4]);
            uint32_t a3 = __float_as_uint(PA[8*PST + k0 + 4]);
            #pragma unroll
            for (int nt = 0; nt < 16; nt++) {
                const int nb = wn*128 + nt*8 + g;
                uint32_t b0 = __float_as_uint(Vs[k0*VP + nb]);
                uint32_t b1 = __float_as_uint(Vs[(k0+4)*VP + nb]);
                mma8(o[nt], a0, a1, a2, a3, b0, b1);
            }
        }
    }

    // ---- write out ---------------------------------------------------------
    float inv0 = 1.0f / l0;
    float inv1 = 1.0f / l1;
    float* Og = O + ((size_t)b*TT + (size_t)qi*FBM) * DIM;
    #pragma unroll
    for (int nt = 0; nt < 16; nt++) {
        int col = wn*128 + nt*8 + 2*t;
        *(float2*)(Og + (size_t)row0*DIM + col) =
            make_float2(o[nt][0]*inv0, o[nt][1]*inv0);
        *(float2*)(Og + (size_t)(row0+8)*DIM + col) =
            make_float2(o[nt][2]*inv1, o[nt][3]*inv1);
    }
}

// ---------------- launch ---------------------------------------------------
extern "C" void kernel_launch(void* const* d_in, const int* in_sizes, int n_in,
                              void* d_out, int out_size)
{
    const float* x           = (const float*)d_in[0];
    const float* attn_norm_w = (const float*)d_in[1];
    const float* mlp_norm_w  = (const float*)d_in[2];
    const float* wq = (const float*)d_in[3];  const float* bq = (const float*)d_in[4];
    const float* wk = (const float*)d_in[5];  const float* bk = (const float*)d_in[6];
    const float* wv = (const float*)d_in[7];  const float* bv = (const float*)d_in[8];
    const float* wo = (const float*)d_in[9];  const float* bo = (const float*)d_in[10];
    const float* w1 = (const float*)d_in[11]; const float* b1 = (const float*)d_in[12];
    const float* w2 = (const float*)d_in[13]; const float* b2 = (const float*)d_in[14];
    float* out = (float*)d_out;

    float *xn, *q, *k, *v, *attn, *x2, *hn, *h;
    cudaGetSymbolAddress((void**)&xn,   g_xn);
    cudaGetSymbolAddress((void**)&q,    g_q);
    cudaGetSymbolAddress((void**)&k,    g_k);
    cudaGetSymbolAddress((void**)&v,    g_v);
    cudaGetSymbolAddress((void**)&attn, g_attn);
    cudaGetSymbolAddress((void**)&x2,   g_x2);
    cudaGetSymbolAddress((void**)&hn,   g_hn);
    cudaGetSymbolAddress((void**)&h,    g_h);

    cudaFuncSetAttribute(flash_mma_kernel,
                         cudaFuncAttributeMaxDynamicSharedMemorySize,
                         FLASH_SMEM_BYTES);

    // 1. attention-branch RMSNorm
    rmsnorm_kernel<<<ROWS, 256>>>(x, attn_norm_w, xn);

    // 2. QKV projections (SIMT fp32)
    dim3 g256(DIM/GBN, ROWS/GBM);   // (2,128)
    gemm_kernel<EPI_NONE><<<g256, 256>>>(xn, wq, bq, nullptr, q, ROWS, DIM, DIM);
    gemm_kernel<EPI_NONE><<<g256, 256>>>(xn, wk, bk, nullptr, k, ROWS, DIM, DIM);
    gemm_kernel<EPI_NONE><<<g256, 256>>>(xn, wv, bv, nullptr, v, ROWS, DIM, DIM);

    // 3. causal attention (tensor cores, tf32)
    flash_mma_kernel<<<dim3(TT/FBM, BB), 256, FLASH_SMEM_BYTES>>>(q, k, v, attn);

    // 4. output projection + residual
    gemm_kernel<EPI_RES><<<g256, 256>>>(attn, wo, bo, x, x2, ROWS, DIM, DIM);

    // 5. MLP-branch RMSNorm
    rmsnorm_kernel<<<ROWS, 256>>>(x2, mlp_norm_w, hn);

    // 6. MLP up + GELU
    dim3 g1024(4*DIM/GBN, ROWS/GBM);  // (8,128)
    gemm_kernel<EPI_GELU><<<g1024, 256>>>(hn, w1, b1, nullptr, h, ROWS, 4*DIM, DIM);

    // 7. MLP down + residual -> out
    gemm_kernel<EPI_RES><<<g256, 256>>>(h, w2, b2, x2, out, ROWS, DIM, 4*DIM);
}

// round 7
// speedup vs baseline: 5.0014x; 1.5658x over previous
#include <cuda_runtime.h>
#include <cuda_bf16.h>
#include <math.h>
#include <cstdint>

#define DIM 256
#define BB  4
#define TT  4096
#define ROWS (BB*TT)          // 16384

// ---------------- scratch (device globals; no allocation allowed) ----------
__device__ float g_xn  [ROWS*DIM];
__device__ float g_q   [ROWS*DIM];
__device__ float g_k   [ROWS*DIM];
__device__ float g_v   [ROWS*DIM];
__device__ float g_attn[ROWS*DIM];
__device__ float g_x2  [ROWS*DIM];
__device__ float g_hn  [ROWS*DIM];
__device__ float g_h   [ROWS*4*DIM];

// ---------------- helpers ---------------------------------------------------
__device__ __forceinline__ float f2tf32(float x) {
    uint32_t u = __float_as_uint(x);
    asm("cvt.rna.tf32.f32 %0, %0;" : "+r"(u));
    return __uint_as_float(u);
}
__device__ __forceinline__ void mma8(float* c,
                                     uint32_t a0, uint32_t a1, uint32_t a2, uint32_t a3,
                                     uint32_t b0, uint32_t b1) {
    asm volatile(
        "mma.sync.aligned.m16n8k8.row.col.f32.tf32.tf32.f32 "
        "{%0,%1,%2,%3}, {%4,%5,%6,%7}, {%8,%9}, {%0,%1,%2,%3};"
        : "+f"(c[0]), "+f"(c[1]), "+f"(c[2]), "+f"(c[3])
        : "r"(a0), "r"(a1), "r"(a2), "r"(a3), "r"(b0), "r"(b1));
}
__device__ __forceinline__ uint32_t smem_u32(const void* p) {
    uint32_t a;
    asm("{ .reg .u64 t; cvta.to.shared.u64 t, %1; cvt.u32.u64 %0, t; }" : "=r"(a) : "l"(p));
    return a;
}
__device__ __forceinline__ void cp16(uint32_t dst, const void* src) {
    asm volatile("cp.async.cg.shared.global [%0], [%1], 16;" :: "r"(dst), "l"(src));
}
#define CP_COMMIT() asm volatile("cp.async.commit_group;" ::: "memory")
#define CP_WAIT1()  asm volatile("cp.async.wait_group 1;"  ::: "memory")

// ---------------- RMSNorm ---------------------------------------------------
__global__ void rmsnorm_kernel(const float* __restrict__ x,
                               const float* __restrict__ w,
                               float* __restrict__ out)
{
    int row = blockIdx.x;
    int t   = threadIdx.x;
    float v = x[(size_t)row*DIM + t];
    float s = v*v;
    #pragma unroll
    for (int o = 16; o; o >>= 1) s += __shfl_xor_sync(0xffffffffu, s, o);
    __shared__ float ws[8];
    if ((t & 31) == 0) ws[t >> 5] = s;
    __syncthreads();
    float tot = ws[0]+ws[1]+ws[2]+ws[3]+ws[4]+ws[5]+ws[6]+ws[7];
    float inv = rsqrtf(tot * (1.0f/DIM) + 1e-6f);
    out[(size_t)row*DIM + t] = v * inv * w[t];
}

// ---------------- tensor-core tf32 GEMM: C = epi(A @ W^T + bias [+R]) ------
// CTA 128x128, 8 warps (4m x 2n), warp tile 32x64. BK=32, 3-stage cp.async.
enum { EPI_NONE = 0, EPI_RES = 1, EPI_GELU = 2 };

#define BKC 32
#define LDK 36                     // padded row stride (floats)
#define ATILE_B (128*LDK*4)        // 18432 bytes
#define STG_B   (2*ATILE_B)        // 36864 bytes per stage
#define GEMM_SMEM_BYTES (3*STG_B)  // 110592

template<int EPI>
__global__ void __launch_bounds__(256, 1)
gemm_mma(const float* __restrict__ A, const float* __restrict__ W,
         const float* __restrict__ bias, const float* __restrict__ R,
         float* __restrict__ C, int M, int N, int K)
{
    extern __shared__ float sm[];
    const uint32_t sb = smem_u32(sm);

    const int tid  = threadIdx.x;
    const int wid  = tid >> 5;
    const int lane = tid & 31;
    const int wm   = wid & 3;        // m-warp (rows wm*32)
    const int wn   = wid >> 2;       // n-warp (cols wn*64)
    const int g    = lane >> 2;
    const int t    = lane & 3;
    const int mBase = blockIdx.y * 128;
    const int nBase = blockIdx.x * 128;

    const int r_ld  = tid >> 3;          // 0..31 rows per 256-thread pass? (see below)
    const int c4_ld = (tid & 7) << 2;

    // stage loader: 128 rows x 32 floats for A and W each
    auto load_stage = [&](int s, int c) {
        const uint32_t base = sb + (uint32_t)s * STG_B;
        const float* Ag = A + (size_t)mBase * K + c * BKC;
        const float* Wg = W + (size_t)nBase * K + c * BKC;
        #pragma unroll
        for (int i = 0; i < 4; i++) {
            int r = r_ld + i * 32;
            cp16(base + (uint32_t)(r*LDK + c4_ld)*4,           Ag + (size_t)r*K + c4_ld);
            cp16(base + ATILE_B + (uint32_t)(r*LDK + c4_ld)*4, Wg + (size_t)r*K + c4_ld);
        }
    };

    const int nch = K / BKC;

    load_stage(0, 0); CP_COMMIT();
    load_stage(1, 1); CP_COMMIT();

    float acc[2][8][4];
    #pragma unroll
    for (int mf = 0; mf < 2; mf++)
        #pragma unroll
        for (int nf = 0; nf < 8; nf++)
            #pragma unroll
            for (int j = 0; j < 4; j++) acc[mf][nf][j] = 0.f;

    for (int c = 0; c < nch; c++) {
        CP_WAIT1();
        __syncthreads();

        int cn = c + 2;
        if (cn < nch) load_stage(cn % 3, cn);
        CP_COMMIT();

        const float* As = sm + (size_t)(c % 3) * (STG_B/4);
        const float* Bs = As + ATILE_B/4;

        #pragma unroll
        for (int k8 = 0; k8 < 4; k8++) {
            const int k0 = k8*8 + t;
            uint32_t a[2][4];
            #pragma unroll
            for (int mf = 0; mf < 2; mf++) {
                const float* AR = As + (wm*32 + mf*16 + g)*LDK;
                a[mf][0] = __float_as_uint(AR[k0]);
                a[mf][1] = __float_as_uint(AR[8*LDK + k0]);
                a[mf][2] = __float_as_uint(AR[k0 + 4]);
                a[mf][3] = __float_as_uint(AR[8*LDK + k0 + 4]);
            }
            #pragma unroll
            for (int nf = 0; nf < 8; nf++) {
                const float* BR = Bs + (wn*64 + nf*8 + g)*LDK + k0;
                uint32_t b0 = __float_as_uint(BR[0]);
                uint32_t b1 = __float_as_uint(BR[4]);
                mma8(acc[0][nf], a[0][0], a[0][1], a[0][2], a[0][3], b0, b1);
                mma8(acc[1][nf], a[1][0], a[1][1], a[1][2], a[1][3], b0, b1);
            }
        }
    }

    // ---- epilogue: bias (+gelu / +residual), direct float2 stores ----------
    #pragma unroll
    for (int nf = 0; nf < 8; nf++) {
        const int col = nBase + wn*64 + nf*8 + 2*t;
        const float b0 = bias[col], b1 = bias[col+1];
        #pragma unroll
        for (int mf = 0; mf < 2; mf++) {
            const int row = mBase + wm*32 + mf*16 + g;
            #pragma unroll
            for (int h = 0; h < 2; h++) {       // row, row+8
                size_t off = (size_t)(row + h*8) * N + col;
                float v0 = acc[mf][nf][h*2+0] + b0;
                float v1 = acc[mf][nf][h*2+1] + b1;
                if (EPI == EPI_GELU) {
                    v0 = 0.5f*v0*(1.0f + erff(v0*0.70710678118654752f));
                    v1 = 0.5f*v1*(1.0f + erff(v1*0.70710678118654752f));
                }
                if (EPI == EPI_RES) {
                    float2 rr = *(const float2*)&R[off];
                    v0 += rr.x; v1 += rr.y;
                }
                *(float2*)&C[off] = make_float2(v0, v1);
            }
        }
    }
}

// ---------------- flash attention: mma.sync tf32, causal, d=256 ------------
#define FBM 64
#define FBN 64
#define QP 260
#define KP 260
#define VP 264
#define PST 68
#define FLASH_SMEM_BYTES ((64*QP + 64*KP + 64*VP + 64*PST + 256) * 4)  // 219136

__global__ void __launch_bounds__(256, 1)
flash_mma_kernel(const float* __restrict__ Q, const float* __restrict__ K,
                 const float* __restrict__ V, float* __restrict__ O)
{
    extern __shared__ float sm[];
    float* Qs   = sm;
    float* Ks   = Qs + 64*QP;
    float* Vs   = Ks + 64*KP;
    float* Ps   = Vs + 64*VP;
    float* pmax = Ps + 64*PST;
    float* psum = pmax + 128;

    const int qi  = gridDim.x - 1 - blockIdx.x;
    const int b   = blockIdx.y;
    const int tid = threadIdx.x;
    const int wid = tid >> 5;
    const int lane = tid & 31;
    const int wm = wid & 3;
    const int wn = wid >> 2;
    const int g  = lane >> 2;
    const int t  = lane & 3;

    const float scale = 0.0625f;
    const float* Qg = Q + ((size_t)b*TT + (size_t)qi*FBM) * DIM;

    #pragma unroll
    for (int i = 0; i < 16; i++) {
        int f  = tid + i*256;
        int r  = f >> 6;
        int c4 = (f & 63) << 2;
        float4 qv = *(const float4*)(Qg + (size_t)r*DIM + c4);
        *(float4*)(Qs + r*QP + c4) = make_float4(
            f2tf32(qv.x*scale), f2tf32(qv.y*scale),
            f2tf32(qv.z*scale), f2tf32(qv.w*scale));
    }

    float o[16][4];
    #pragma unroll
    for (int i = 0; i < 16; i++)
        #pragma unroll
        for (int j = 0; j < 4; j++) o[i][j] = 0.f;
    float m0 = -1e30f, m1 = -1e30f, l0 = 0.f, l1 = 0.f;

    const int row0 = wm*16 + g;
    const float* QA = Qs + row0*QP;

    for (int kj = 0; kj <= qi; kj++) {
        const float* Kg = K + ((size_t)b*TT + (size_t)kj*FBN) * DIM;
        const float* Vg = V + ((size_t)b*TT + (size_t)kj*FBN) * DIM;

        __syncthreads();
        #pragma unroll
        for (int i = 0; i < 16; i++) {
            int f  = tid + i*256;
            int r  = f >> 6;
            int c4 = (f & 63) << 2;
            float4 kv = *(const float4*)(Kg + (size_t)r*DIM + c4);
            *(float4*)(Ks + r*KP + c4) = make_float4(
                f2tf32(kv.x), f2tf32(kv.y), f2tf32(kv.z), f2tf32(kv.w));
            float4 vv = *(const float4*)(Vg + (size_t)r*DIM + c4);
            *(float4*)(Vs + r*VP + c4) = make_float4(
                f2tf32(vv.x), f2tf32(vv.y), f2tf32(vv.z), f2tf32(vv.w));
        }
        __syncthreads();

        float s[4][4];
        #pragma unroll
        for (int nt = 0; nt < 4; nt++)
            #pragma unroll
            for (int j = 0; j < 4; j++) s[nt][j] = 0.f;

        #pragma unroll 4
        for (int k8 = 0; k8 < 32; k8++) {
            const int k0 = k8*8 + t;
            uint32_t a0 = __float_as_uint(QA[k0]);
            uint32_t a1 = __float_as_uint(QA[8*QP + k0]);
            uint32_t a2 = __float_as_uint(QA[k0 + 4]);
            uint32_t a3 = __float_as_uint(QA[8*QP + k0 + 4]);
            #pragma unroll
            for (int nt = 0; nt < 4; nt++) {
                const float* KB = Ks + (wn*32 + nt*8 + g)*KP + k0;
                uint32_t b0 = __float_as_uint(KB[0]);
                uint32_t b1 = __float_as_uint(KB[4]);
                mma8(s[nt], a0, a1, a2, a3, b0, b1);
            }
        }

        if (kj == qi) {
            #pragma unroll
            for (int nt = 0; nt < 4; nt++) {
                int col = wn*32 + nt*8 + 2*t;
                if (col     > row0)     s[nt][0] = -1e30f;
                if (col + 1 > row0)     s[nt][1] = -1e30f;
                if (col     > row0 + 8) s[nt][2] = -1e30f;
                if (col + 1 > row0 + 8) s[nt][3] = -1e30f;
            }
        }

        float pm0 = -1e30f, pm1 = -1e30f;
        #pragma unroll
        for (int nt = 0; nt < 4; nt++) {
            pm0 = fmaxf(pm0, fmaxf(s[nt][0], s[nt][1]));
            pm1 = fmaxf(pm1, fmaxf(s[nt][2], s[nt][3]));
        }
        pm0 = fmaxf(pm0, __shfl_xor_sync(0xffffffffu, pm0, 1));
        pm0 = fmaxf(pm0, __shfl_xor_sync(0xffffffffu, pm0, 2));
        pm1 = fmaxf(pm1, __shfl_xor_sync(0xffffffffu, pm1, 1));
        pm1 = fmaxf(pm1, __shfl_xor_sync(0xffffffffu, pm1, 2));
        if (t == 0) {
            pmax[wn*64 + row0]     = pm0;
            pmax[wn*64 + row0 + 8] = pm1;
        }
        __syncthreads();

        float nm0 = fmaxf(m0, fmaxf(pmax[row0],     pmax[64 + row0]));
        float nm1 = fmaxf(m1, fmaxf(pmax[row0 + 8], pmax[64 + row0 + 8]));
        float alpha0 = __expf(m0 - nm0);
        float alpha1 = __expf(m1 - nm1);
        m0 = nm0; m1 = nm1;

        float rs0 = 0.f, rs1 = 0.f;
        #pragma unroll
        for (int nt = 0; nt < 4; nt++) {
            s[nt][0] = __expf(s[nt][0] - nm0);
            s[nt][1] = __expf(s[nt][1] - nm0);
            s[nt][2] = __expf(s[nt][2] - nm1);
            s[nt][3] = __expf(s[nt][3] - nm1);
            rs0 += s[nt][0] + s[nt][1];
            rs1 += s[nt][2] + s[nt][3];
            int col = wn*32 + nt*8 + 2*t;
            *(float2*)(Ps + row0*PST + col) =
                make_float2(f2tf32(s[nt][0]), f2tf32(s[nt][1]));
            *(float2*)(Ps + (row0+8)*PST + col) =
                make_float2(f2tf32(s[nt][2]), f2tf32(s[nt][3]));
        }
        rs0 += __shfl_xor_sync(0xffffffffu, rs0, 1);
        rs0 += __shfl_xor_sync(0xffffffffu, rs0, 2);
        rs1 += __shfl_xor_sync(0xffffffffu, rs1, 1);
        rs1 += __shfl_xor_sync(0xffffffffu, rs1, 2);
        if (t == 0) {
            psum[wn*64 + row0]     = rs0;
            psum[wn*64 + row0 + 8] = rs1;
        }
        __syncthreads();

        l0 = l0*alpha0 + psum[row0]     + psum[64 + row0];
        l1 = l1*alpha1 + psum[row0 + 8] + psum[64 + row0 + 8];

        #pragma unroll
        for (int nt = 0; nt < 16; nt++) {
            o[nt][0] *= alpha0; o[nt][1] *= alpha0;
            o[nt][2] *= alpha1; o[nt][3] *= alpha1;
        }

        const float* PA = Ps + row0*PST;
        #pragma unroll
        for (int k8 = 0; k8 < 8; k8++) {
            const int k0 = k8*8 + t;
            uint32_t a0 = __float_as_uint(PA[k0]);
            uint32_t a1 = __float_as_uint(PA[8*PST + k0]);
            uint32_t a2 = __float_as_uint(PA[k0 + 4]);
            uint32_t a3 = __float_as_uint(PA[8*PST + k0 + 4]);
            #pragma unroll
            for (int nt = 0; nt < 16; nt++) {
                const int nb = wn*128 + nt*8 + g;
                uint32_t b0 = __float_as_uint(Vs[k0*VP + nb]);
                uint32_t b1 = __float_as_uint(Vs[(k0+4)*VP + nb]);
                mma8(o[nt], a0, a1, a2, a3, b0, b1);
            }
        }
    }

    float inv0 = 1.0f / l0;
    float inv1 = 1.0f / l1;
    float* Og = O + ((size_t)b*TT + (size_t)qi*FBM) * DIM;
    #pragma unroll
    for (int nt = 0; nt < 16; nt++) {
        int col = wn*128 + nt*8 + 2*t;
        *(float2*)(Og + (size_t)row0*DIM + col) =
            make_float2(o[nt][0]*inv0, o[nt][1]*inv0);
        *(float2*)(Og + (size_t)(row0+8)*DIM + col) =
            make_float2(o[nt][2]*inv1, o[nt][3]*inv1);
    }
}

// ---------------- launch ---------------------------------------------------
extern "C" void kernel_launch(void* const* d_in, const int* in_sizes, int n_in,
                              void* d_out, int out_size)
{
    const float* x           = (const float*)d_in[0];
    const float* attn_norm_w = (const float*)d_in[1];
    const float* mlp_norm_w  = (const float*)d_in[2];
    const float* wq = (const float*)d_in[3];  const float* bq = (const float*)d_in[4];
    const float* wk = (const float*)d_in[5];  const float* bk = (const float*)d_in[6];
    const float* wv = (const float*)d_in[7];  const float* bv = (const float*)d_in[8];
    const float* wo = (const float*)d_in[9];  const float* bo = (const float*)d_in[10];
    const float* w1 = (const float*)d_in[11]; const float* b1 = (const float*)d_in[12];
    const float* w2 = (const float*)d_in[13]; const float* b2 = (const float*)d_in[14];
    float* out = (float*)d_out;

    float *xn, *q, *k, *v, *attn, *x2, *hn, *h;
    cudaGetSymbolAddress((void**)&xn,   g_xn);
    cudaGetSymbolAddress((void**)&q,    g_q);
    cudaGetSymbolAddress((void**)&k,    g_k);
    cudaGetSymbolAddress((void**)&v,    g_v);
    cudaGetSymbolAddress((void**)&attn, g_attn);
    cudaGetSymbolAddress((void**)&x2,   g_x2);
    cudaGetSymbolAddress((void**)&hn,   g_hn);
    cudaGetSymbolAddress((void**)&h,    g_h);

    cudaFuncSetAttribute(flash_mma_kernel,
                         cudaFuncAttributeMaxDynamicSharedMemorySize, FLASH_SMEM_BYTES);
    cudaFuncSetAttribute(gemm_mma<EPI_NONE>,
                         cudaFuncAttributeMaxDynamicSharedMemorySize, GEMM_SMEM_BYTES);
    cudaFuncSetAttribute(gemm_mma<EPI_RES>,
                         cudaFuncAttributeMaxDynamicSharedMemorySize, GEMM_SMEM_BYTES);
    cudaFuncSetAttribute(gemm_mma<EPI_GELU>,
                         cudaFuncAttributeMaxDynamicSharedMemorySize, GEMM_SMEM_BYTES);

    // 1. attention-branch RMSNorm
    rmsnorm_kernel<<<ROWS, 256>>>(x, attn_norm_w, xn);

    // 2. QKV projections (tensor cores)
    dim3 g256(DIM/128, ROWS/128);   // (2,128)
    gemm_mma<EPI_NONE><<<g256, 256, GEMM_SMEM_BYTES>>>(xn, wq, bq, nullptr, q, ROWS, DIM, DIM);
    gemm_mma<EPI_NONE><<<g256, 256, GEMM_SMEM_BYTES>>>(xn, wk, bk, nullptr, k, ROWS, DIM, DIM);
    gemm_mma<EPI_NONE><<<g256, 256, GEMM_SMEM_BYTES>>>(xn, wv, bv, nullptr, v, ROWS, DIM, DIM);

    // 3. causal attention (tensor cores)
    flash_mma_kernel<<<dim3(TT/FBM, BB), 256, FLASH_SMEM_BYTES>>>(q, k, v, attn);

    // 4. output projection + residual
    gemm_mma<EPI_RES><<<g256, 256, GEMM_SMEM_BYTES>>>(attn, wo, bo, x, x2, ROWS, DIM, DIM);

    // 5. MLP-branch RMSNorm
    rmsnorm_kernel<<<ROWS, 256>>>(x2, mlp_norm_w, hn);

    // 6. MLP up + GELU
    dim3 g1024(4*DIM/128, ROWS/128);  // (8,128)
    gemm_mma<EPI_GELU><<<g1024, 256, GEMM_SMEM_BYTES>>>(hn, w1, b1, nullptr, h, ROWS, 4*DIM, DIM);

    // 7. MLP down + residual -> out
    gemm_mma<EPI_RES><<<g256, 256, GEMM_SMEM_BYTES>>>(h, w2, b2, x2, out, ROWS, DIM, 4*DIM);
}

// round 8
// speedup vs baseline: 5.5116x; 1.1020x over previous
#include <cuda_runtime.h>
#include <cuda_bf16.h>
#include <math.h>
#include <cstdint>

#define DIM 256
#define BB  4
#define TT  4096
#define ROWS (BB*TT)          // 16384

// ---------------- scratch (device globals; no allocation allowed) ----------
__device__ float g_xn  [ROWS*DIM];
__device__ float g_q   [ROWS*DIM];
__device__ float g_k   [ROWS*DIM];
__device__ float g_v   [ROWS*DIM];
__device__ float g_attn[ROWS*DIM];
__device__ float g_x2  [ROWS*DIM];
__device__ float g_hn  [ROWS*DIM];
__device__ float g_h   [ROWS*4*DIM];

// ---------------- helpers ---------------------------------------------------
__device__ __forceinline__ float f2tf32(float x) {
    uint32_t u = __float_as_uint(x);
    asm("cvt.rna.tf32.f32 %0, %0;" : "+r"(u));
    return __uint_as_float(u);
}
__device__ __forceinline__ void mma8(float* c,
                                     uint32_t a0, uint32_t a1, uint32_t a2, uint32_t a3,
                                     uint32_t b0, uint32_t b1) {
    asm volatile(
        "mma.sync.aligned.m16n8k8.row.col.f32.tf32.tf32.f32 "
        "{%0,%1,%2,%3}, {%4,%5,%6,%7}, {%8,%9}, {%0,%1,%2,%3};"
        : "+f"(c[0]), "+f"(c[1]), "+f"(c[2]), "+f"(c[3])
        : "r"(a0), "r"(a1), "r"(a2), "r"(a3), "r"(b0), "r"(b1));
}
__device__ __forceinline__ uint32_t smem_u32(const void* p) {
    uint32_t a;
    asm("{ .reg .u64 t; cvta.to.shared.u64 t, %1; cvt.u32.u64 %0, t; }" : "=r"(a) : "l"(p));
    return a;
}
__device__ __forceinline__ void cp16(uint32_t dst, const void* src) {
    asm volatile("cp.async.cg.shared.global [%0], [%1], 16;" :: "r"(dst), "l"(src));
}
#define CP_COMMIT() asm volatile("cp.async.commit_group;" ::: "memory")
#define CP_WAIT1()  asm volatile("cp.async.wait_group 1;"  ::: "memory")
#define CP_WAIT0()  asm volatile("cp.async.wait_group 0;"  ::: "memory")

// ---------------- RMSNorm ---------------------------------------------------
__global__ void rmsnorm_kernel(const float* __restrict__ x,
                               const float* __restrict__ w,
                               float* __restrict__ out)
{
    int row = blockIdx.x;
    int t   = threadIdx.x;
    float v = x[(size_t)row*DIM + t];
    float s = v*v;
    #pragma unroll
    for (int o = 16; o; o >>= 1) s += __shfl_xor_sync(0xffffffffu, s, o);
    __shared__ float ws[8];
    if ((t & 31) == 0) ws[t >> 5] = s;
    __syncthreads();
    float tot = ws[0]+ws[1]+ws[2]+ws[3]+ws[4]+ws[5]+ws[6]+ws[7];
    float inv = rsqrtf(tot * (1.0f/DIM) + 1e-6f);
    out[(size_t)row*DIM + t] = v * inv * w[t];
}

// ---------------- tensor-core tf32 GEMM: C = epi(A @ W^T + bias [+R]) ------
// CTA 128x128, 512 threads = 16 warps (4m x 4n), warp tile 32x32.
// BK=32, 3-stage cp.async pipeline.
enum { EPI_NONE = 0, EPI_RES = 1, EPI_GELU = 2 };

#define BKC 32
#define LDK 36                     // padded row stride (floats)
#define ATILE_B (128*LDK*4)        // 18432 bytes
#define STG_B   (2*ATILE_B)        // 36864 bytes per stage
#define GEMM_SMEM_BYTES (3*STG_B)  // 110592

template<int EPI>
__global__ void __launch_bounds__(512, 1)
gemm_mma(const float* __restrict__ A, const float* __restrict__ W,
         const float* __restrict__ bias, const float* __restrict__ R,
         float* __restrict__ C, int M, int N, int K)
{
    extern __shared__ float sm[];
    const uint32_t sb = smem_u32(sm);

    const int tid  = threadIdx.x;
    const int wid  = tid >> 5;
    const int lane = tid & 31;
    const int wm   = wid & 3;        // m-warp (rows wm*32)
    const int wn   = wid >> 2;       // n-warp (cols wn*32)
    const int g    = lane >> 2;
    const int t    = lane & 3;
    const int mBase = blockIdx.y * 128;
    const int nBase = blockIdx.x * 128;

    const int r_ld  = tid >> 3;          // 0..63
    const int c4_ld = (tid & 7) << 2;    // 0..28

    auto load_stage = [&](int s, int c) {
        const uint32_t base = sb + (uint32_t)s * STG_B;
        const float* Ag = A + (size_t)mBase * K + c * BKC;
        const float* Wg = W + (size_t)nBase * K + c * BKC;
        #pragma unroll
        for (int i = 0; i < 2; i++) {
            int r = r_ld + i * 64;
            cp16(base + (uint32_t)(r*LDK + c4_ld)*4,           Ag + (size_t)r*K + c4_ld);
            cp16(base + ATILE_B + (uint32_t)(r*LDK + c4_ld)*4, Wg + (size_t)r*K + c4_ld);
        }
    };

    const int nch = K / BKC;

    load_stage(0, 0); CP_COMMIT();
    load_stage(1, 1); CP_COMMIT();

    float acc[2][4][4];
    #pragma unroll
    for (int mf = 0; mf < 2; mf++)
        #pragma unroll
        for (int nf = 0; nf < 4; nf++)
            #pragma unroll
            for (int j = 0; j < 4; j++) acc[mf][nf][j] = 0.f;

    for (int c = 0; c < nch; c++) {
        CP_WAIT1();
        __syncthreads();

        int cn = c + 2;
        if (cn < nch) load_stage(cn % 3, cn);
        CP_COMMIT();

        const float* As = sm + (size_t)(c % 3) * (STG_B/4);
        const float* Bs = As + ATILE_B/4;

        #pragma unroll
        for (int k8 = 0; k8 < 4; k8++) {
            const int k0 = k8*8 + t;
            uint32_t a[2][4];
            #pragma unroll
            for (int mf = 0; mf < 2; mf++) {
                const float* AR = As + (wm*32 + mf*16 + g)*LDK;
                a[mf][0] = __float_as_uint(AR[k0]);
                a[mf][1] = __float_as_uint(AR[8*LDK + k0]);
                a[mf][2] = __float_as_uint(AR[k0 + 4]);
                a[mf][3] = __float_as_uint(AR[8*LDK + k0 + 4]);
            }
            #pragma unroll
            for (int nf = 0; nf < 4; nf++) {
                const float* BR = Bs + (wn*32 + nf*8 + g)*LDK + k0;
                uint32_t b0 = __float_as_uint(BR[0]);
                uint32_t b1 = __float_as_uint(BR[4]);
                mma8(acc[0][nf], a[0][0], a[0][1], a[0][2], a[0][3], b0, b1);
                mma8(acc[1][nf], a[1][0], a[1][1], a[1][2], a[1][3], b0, b1);
            }
        }
    }

    // ---- epilogue: bias (+gelu / +residual / tf32-round), float2 stores ----
    #pragma unroll
    for (int nf = 0; nf < 4; nf++) {
        const int col = nBase + wn*32 + nf*8 + 2*t;
        const float b0 = bias[col], b1 = bias[col+1];
        #pragma unroll
        for (int mf = 0; mf < 2; mf++) {
            const int row = mBase + wm*32 + mf*16 + g;
            #pragma unroll
            for (int h = 0; h < 2; h++) {       // row, row+8
                size_t off = (size_t)(row + h*8) * N + col;
                float v0 = acc[mf][nf][h*2+0] + b0;
                float v1 = acc[mf][nf][h*2+1] + b1;
                if (EPI == EPI_GELU) {
                    v0 = 0.5f*v0*(1.0f + erff(v0*0.70710678118654752f));
                    v1 = 0.5f*v1*(1.0f + erff(v1*0.70710678118654752f));
                }
                if (EPI == EPI_RES) {
                    float2 rr = *(const float2*)&R[off];
                    v0 += rr.x; v1 += rr.y;
                }
                if (EPI == EPI_NONE) {   // QKV outputs: pre-round to tf32 so
                    v0 = f2tf32(v0);     // flash's cp.async truncation is exact
                    v1 = f2tf32(v1);
                }
                *(float2*)&C[off] = make_float2(v0, v1);
            }
        }
    }
}

// ---------------- flash attention: mma.sync tf32, cp.async pipelined -------
#define FBM 64
#define FBN 64
#define QP 260
#define KP 260
#define VP 264
#define PST 68
#define FLASH_SMEM_BYTES ((64*QP + 64*KP + 64*VP + 64*PST + 256) * 4)  // 219136

__global__ void __launch_bounds__(256, 1)
flash_mma_kernel(const float* __restrict__ Q, const float* __restrict__ K,
                 const float* __restrict__ V, float* __restrict__ O)
{
    extern __shared__ float sm[];
    float* Qs   = sm;
    float* Ks   = Qs + 64*QP;
    float* Vs   = Ks + 64*KP;
    float* Ps   = Vs + 64*VP;
    float* pmax = Ps + 64*PST;
    float* psum = pmax + 128;

    const int qi  = gridDim.x - 1 - blockIdx.x;   // heavy tiles first
    const int b   = blockIdx.y;
    const int tid = threadIdx.x;
    const int wid = tid >> 5;
    const int lane = tid & 31;
    const int wm = wid & 3;
    const int wn = wid >> 2;
    const int g  = lane >> 2;
    const int t  = lane & 3;

    const uint32_t ks_u = smem_u32(Ks);
    const uint32_t vs_u = smem_u32(Vs);

    const float scale = 0.0625f;   // 1/sqrt(256), power of 2: preserves tf32
    const float* Qg = Q + ((size_t)b*TT + (size_t)qi*FBM) * DIM;
    const float* Kb = K + (size_t)b*TT*DIM;
    const float* Vb = V + (size_t)b*TT*DIM;

    // cp.async a 64x256 tile into padded smem (stride in floats)
    auto cp_tile = [&](uint32_t dst_u, const float* src, int pad) {
        #pragma unroll
        for (int i = 0; i < 16; i++) {
            int f  = tid + i*256;
            int r  = f >> 6;
            int c4 = (f & 63) << 2;
            cp16(dst_u + (uint32_t)(r*pad + c4)*4, src + (size_t)r*DIM + c4);
        }
    };

    // load Q tile (values already tf32-rounded by producer GEMM)
    #pragma unroll
    for (int i = 0; i < 16; i++) {
        int f  = tid + i*256;
        int r  = f >> 6;
        int c4 = (f & 63) << 2;
        float4 qv = *(const float4*)(Qg + (size_t)r*DIM + c4);
        *(float4*)(Qs + r*QP + c4) = make_float4(
            qv.x*scale, qv.y*scale, qv.z*scale, qv.w*scale);
    }

    cp_tile(ks_u, Kb, KP); CP_COMMIT();            // K(0)
    cp_tile(vs_u, Vb, VP); CP_COMMIT();            // V(0)

    float o[16][4];
    #pragma unroll
    for (int i = 0; i < 16; i++)
        #pragma unroll
        for (int j = 0; j < 4; j++) o[i][j] = 0.f;
    float m0 = -1e30f, m1 = -1e30f, l0 = 0.f, l1 = 0.f;

    const int row0 = wm*16 + g;
    const float* QA = Qs + row0*QP;

    for (int kj = 0; kj <= qi; kj++) {
        if (kj > 0) {
            __syncthreads();                        // PV(kj-1) done: Vs free
            cp_tile(vs_u, Vb + (size_t)kj*FBN*DIM, VP); CP_COMMIT();  // V(kj)
        }
        CP_WAIT1();                                 // K(kj) arrived
        __syncthreads();

        // ---- S = Q K^T ----------------------------------------------------
        float s[4][4];
        #pragma unroll
        for (int nt = 0; nt < 4; nt++)
            #pragma unroll
            for (int j = 0; j < 4; j++) s[nt][j] = 0.f;

        #pragma unroll 4
        for (int k8 = 0; k8 < 32; k8++) {
            const int k0 = k8*8 + t;
            uint32_t a0 = __float_as_uint(QA[k0]);
            uint32_t a1 = __float_as_uint(QA[8*QP + k0]);
            uint32_t a2 = __float_as_uint(QA[k0 + 4]);
            uint32_t a3 = __float_as_uint(QA[8*QP + k0 + 4]);
            #pragma unroll
            for (int nt = 0; nt < 4; nt++) {
                const float* KB = Ks + (wn*32 + nt*8 + g)*KP + k0;
                uint32_t b0 = __float_as_uint(KB[0]);
                uint32_t b1 = __float_as_uint(KB[4]);
                mma8(s[nt], a0, a1, a2, a3, b0, b1);
            }
        }

        if (kj == qi) {   // causal mask on diagonal tile
            #pragma unroll
            for (int nt = 0; nt < 4; nt++) {
                int col = wn*32 + nt*8 + 2*t;
                if (col     > row0)     s[nt][0] = -1e30f;
                if (col + 1 > row0)     s[nt][1] = -1e30f;
                if (col     > row0 + 8) s[nt][2] = -1e30f;
                if (col + 1 > row0 + 8) s[nt][3] = -1e30f;
            }
        }

        // ---- online softmax ------------------------------------------------
        float pm0 = -1e30f, pm1 = -1e30f;
        #pragma unroll
        for (int nt = 0; nt < 4; nt++) {
            pm0 = fmaxf(pm0, fmaxf(s[nt][0], s[nt][1]));
            pm1 = fmaxf(pm1, fmaxf(s[nt][2], s[nt][3]));
        }
        pm0 = fmaxf(pm0, __shfl_xor_sync(0xffffffffu, pm0, 1));
        pm0 = fmaxf(pm0, __shfl_xor_sync(0xffffffffu, pm0, 2));
        pm1 = fmaxf(pm1, __shfl_xor_sync(0xffffffffu, pm1, 1));
        pm1 = fmaxf(pm1, __shfl_xor_sync(0xffffffffu, pm1, 2));
        if (t == 0) {
            pmax[wn*64 + row0]     = pm0;
            pmax[wn*64 + row0 + 8] = pm1;
        }
        __syncthreads();

        float nm0 = fmaxf(m0, fmaxf(pmax[row0],     pmax[64 + row0]));
        float nm1 = fmaxf(m1, fmaxf(pmax[row0 + 8], pmax[64 + row0 + 8]));
        float alpha0 = __expf(m0 - nm0);
        float alpha1 = __expf(m1 - nm1);
        m0 = nm0; m1 = nm1;

        float rs0 = 0.f, rs1 = 0.f;
        #pragma unroll
        for (int nt = 0; nt < 4; nt++) {
            s[nt][0] = __expf(s[nt][0] - nm0);
            s[nt][1] = __expf(s[nt][1] - nm0);
            s[nt][2] = __expf(s[nt][2] - nm1);
            s[nt][3] = __expf(s[nt][3] - nm1);
            rs0 += s[nt][0] + s[nt][1];
            rs1 += s[nt][2] + s[nt][3];
            int col = wn*32 + nt*8 + 2*t;
            *(float2*)(Ps + row0*PST + col) =
                make_float2(f2tf32(s[nt][0]), f2tf32(s[nt][1]));
            *(float2*)(Ps + (row0+8)*PST + col) =
                make_float2(f2tf32(s[nt][2]), f2tf32(s[nt][3]));
        }
        rs0 += __shfl_xor_sync(0xffffffffu, rs0, 1);
        rs0 += __shfl_xor_sync(0xffffffffu, rs0, 2);
        rs1 += __shfl_xor_sync(0xffffffffu, rs1, 1);
        rs1 += __shfl_xor_sync(0xffffffffu, rs1, 2);
        if (t == 0) {
            psum[wn*64 + row0]     = rs0;
            psum[wn*64 + row0 + 8] = rs1;
        }

        CP_WAIT0();                                 // V(kj) arrived
        __syncthreads();                            // + P/psum staged, Ks free

        if (kj < qi) {                              // prefetch K(kj+1) over PV
            cp_tile(ks_u, Kb + (size_t)(kj+1)*FBN*DIM, KP); CP_COMMIT();
        }

        l0 = l0*alpha0 + psum[row0]     + psum[64 + row0];
        l1 = l1*alpha1 + psum[row0 + 8] + psum[64 + row0 + 8];

        #pragma unroll
        for (int nt = 0; nt < 16; nt++) {
            o[nt][0] *= alpha0; o[nt][1] *= alpha0;
            o[nt][2] *= alpha1; o[nt][3] *= alpha1;
        }

        // ---- O += P V ------------------------------------------------------
        const float* PA = Ps + row0*PST;
        #pragma unroll
        for (int k8 = 0; k8 < 8; k8++) {
            const int k0 = k8*8 + t;
            uint32_t a0 = __float_as_uint(PA[k0]);
            uint32_t a1 = __float_as_uint(PA[8*PST + k0]);
            uint32_t a2 = __float_as_uint(PA[k0 + 4]);
            uint32_t a3 = __float_as_uint(PA[8*PST + k0 + 4]);
            #pragma unroll
            for (int nt = 0; nt < 16; nt++) {
                const int nb = wn*128 + nt*8 + g;
                uint32_t b0 = __float_as_uint(Vs[k0*VP + nb]);
                uint32_t b1 = __float_as_uint(Vs[(k0+4)*VP + nb]);
                mma8(o[nt], a0, a1, a2, a3, b0, b1);
            }
        }
    }

    float inv0 = 1.0f / l0;
    float inv1 = 1.0f / l1;
    float* Og = O + ((size_t)b*TT + (size_t)qi*FBM) * DIM;
    #pragma unroll
    for (int nt = 0; nt < 16; nt++) {
        int col = wn*128 + nt*8 + 2*t;
        *(float2*)(Og + (size_t)row0*DIM + col) =
            make_float2(o[nt][0]*inv0, o[nt][1]*inv0);
        *(float2*)(Og + (size_t)(row0+8)*DIM + col) =
            make_float2(o[nt][2]*inv1, o[nt][3]*inv1);
    }
}

// ---------------- launch ---------------------------------------------------
extern "C" void kernel_launch(void* const* d_in, const int* in_sizes, int n_in,
                              void* d_out, int out_size)
{
    const float* x           = (const float*)d_in[0];
    const float* attn_norm_w = (const float*)d_in[1];
    const float* mlp_norm_w  = (const float*)d_in[2];
    const float* wq = (const float*)d_in[3];  const float* bq = (const float*)d_in[4];
    const float* wk = (const float*)d_in[5];  const float* bk = (const float*)d_in[6];
    const float* wv = (const float*)d_in[7];  const float* bv = (const float*)d_in[8];
    const float* wo = (const float*)d_in[9];  const float* bo = (const float*)d_in[10];
    const float* w1 = (const float*)d_in[11]; const float* b1 = (const float*)d_in[12];
    const float* w2 = (const float*)d_in[13]; const float* b2 = (const float*)d_in[14];
    float* out = (float*)d_out;

    float *xn, *q, *k, *v, *attn, *x2, *hn, *h;
    cudaGetSymbolAddress((void**)&xn,   g_xn);
    cudaGetSymbolAddress((void**)&q,    g_q);
    cudaGetSymbolAddress((void**)&k,    g_k);
    cudaGetSymbolAddress((void**)&v,    g_v);
    cudaGetSymbolAddress((void**)&attn, g_attn);
    cudaGetSymbolAddress((void**)&x2,   g_x2);
    cudaGetSymbolAddress((void**)&hn,   g_hn);
    cudaGetSymbolAddress((void**)&h,    g_h);

    cudaFuncSetAttribute(flash_mma_kernel,
                         cudaFuncAttributeMaxDynamicSharedMemorySize, FLASH_SMEM_BYTES);
    cudaFuncSetAttribute(gemm_mma<EPI_NONE>,
                         cudaFuncAttributeMaxDynamicSharedMemorySize, GEMM_SMEM_BYTES);
    cudaFuncSetAttribute(gemm_mma<EPI_RES>,
                         cudaFuncAttributeMaxDynamicSharedMemorySize, GEMM_SMEM_BYTES);
    cudaFuncSetAttribute(gemm_mma<EPI_GELU>,
                         cudaFuncAttributeMaxDynamicSharedMemorySize, GEMM_SMEM_BYTES);

    // 1. attention-branch RMSNorm
    rmsnorm_kernel<<<ROWS, 256>>>(x, attn_norm_w, xn);

    // 2. QKV projections (tensor cores)
    dim3 g256(DIM/128, ROWS/128);   // (2,128)
    gemm_mma<EPI_NONE><<<g256, 512, GEMM_SMEM_BYTES>>>(xn, wq, bq, nullptr, q, ROWS, DIM, DIM);
    gemm_mma<EPI_NONE><<<g256, 512, GEMM_SMEM_BYTES>>>(xn, wk, bk, nullptr, k, ROWS, DIM, DIM);
    gemm_mma<EPI_NONE><<<g256, 512, GEMM_SMEM_BYTES>>>(xn, wv, bv, nullptr, v, ROWS, DIM, DIM);

    // 3. causal attention (tensor cores, cp.async pipelined)
    flash_mma_kernel<<<dim3(TT/FBM, BB), 256, FLASH_SMEM_BYTES>>>(q, k, v, attn);

    // 4. output projection + residual
    gemm_mma<EPI_RES><<<g256, 512, GEMM_SMEM_BYTES>>>(attn, wo, bo, x, x2, ROWS, DIM, DIM);

    // 5. MLP-branch RMSNorm
    rmsnorm_kernel<<<ROWS, 256>>>(x2, mlp_norm_w, hn);

    // 6. MLP up + GELU
    dim3 g1024(4*DIM/128, ROWS/128);  // (8,128)
    gemm_mma<EPI_GELU><<<g1024, 512, GEMM_SMEM_BYTES>>>(hn, w1, b1, nullptr, h, ROWS, 4*DIM, DIM);

    // 7. MLP down + residual -> out
    gemm_mma<EPI_RES><<<g256, 512, GEMM_SMEM_BYTES>>>(h, w2, b2, x2, out, ROWS, DIM, 4*DIM);
}

// round 9
// speedup vs baseline: 5.7580x; 1.0447x over previous
#include <cuda_runtime.h>
#include <cuda_bf16.h>
#include <math.h>
#include <cstdint>

#define DIM 256
#define BB  4
#define TT  4096
#define ROWS (BB*TT)          // 16384

// ---------------- scratch (device globals; no allocation allowed) ----------
__device__ float g_xn  [ROWS*DIM];
__device__ float g_q   [ROWS*DIM];
__device__ float g_k   [ROWS*DIM];
__device__ float g_v   [ROWS*DIM];
__device__ float g_attn[ROWS*DIM];
__device__ float g_x2  [ROWS*DIM];
__device__ float g_hn  [ROWS*DIM];
__device__ float g_h   [ROWS*4*DIM];

// ---------------- helpers ---------------------------------------------------
__device__ __forceinline__ float f2tf32(float x) {
    uint32_t u = __float_as_uint(x);
    asm("cvt.rna.tf32.f32 %0, %0;" : "+r"(u));
    return __uint_as_float(u);
}
__device__ __forceinline__ void mma8(float* c,
                                     uint32_t a0, uint32_t a1, uint32_t a2, uint32_t a3,
                                     uint32_t b0, uint32_t b1) {
    asm volatile(
        "mma.sync.aligned.m16n8k8.row.col.f32.tf32.tf32.f32 "
        "{%0,%1,%2,%3}, {%4,%5,%6,%7}, {%8,%9}, {%0,%1,%2,%3};"
        : "+f"(c[0]), "+f"(c[1]), "+f"(c[2]), "+f"(c[3])
        : "r"(a0), "r"(a1), "r"(a2), "r"(a3), "r"(b0), "r"(b1));
}
__device__ __forceinline__ uint32_t smem_u32(const void* p) {
    uint32_t a;
    asm("{ .reg .u64 t; cvta.to.shared.u64 t, %1; cvt.u32.u64 %0, t; }" : "=r"(a) : "l"(p));
    return a;
}
__device__ __forceinline__ void cp16(uint32_t dst, const void* src) {
    asm volatile("cp.async.cg.shared.global [%0], [%1], 16;" :: "r"(dst), "l"(src));
}
#define CP_COMMIT() asm volatile("cp.async.commit_group;" ::: "memory")
#define CP_WAIT1()  asm volatile("cp.async.wait_group 1;"  ::: "memory")
#define CP_WAIT0()  asm volatile("cp.async.wait_group 0;"  ::: "memory")

// ---------------- RMSNorm ---------------------------------------------------
__global__ void rmsnorm_kernel(const float* __restrict__ x,
                               const float* __restrict__ w,
                               float* __restrict__ out)
{
    int row = blockIdx.x;
    int t   = threadIdx.x;
    float v = x[(size_t)row*DIM + t];
    float s = v*v;
    #pragma unroll
    for (int o = 16; o; o >>= 1) s += __shfl_xor_sync(0xffffffffu, s, o);
    __shared__ float ws[8];
    if ((t & 31) == 0) ws[t >> 5] = s;
    __syncthreads();
    float tot = ws[0]+ws[1]+ws[2]+ws[3]+ws[4]+ws[5]+ws[6]+ws[7];
    float inv = rsqrtf(tot * (1.0f/DIM) + 1e-6f);
    out[(size_t)row*DIM + t] = v * inv * w[t];
}

// ---------------- tensor-core tf32 GEMM: C = epi(A @ W^T + bias [+R]) ------
// CTA 256(M) x 128(N), 512 threads = 16 warps (4m x 4n), warp tile 64x32.
// BK=32, 3-stage cp.async pipeline. LDS/MMA ratio = 1.5.
enum { EPI_NONE = 0, EPI_RES = 1, EPI_GELU = 2 };

#define BKC 32
#define LDK 36                         // padded row stride (floats)
#define ATILE_B (256*LDK*4)            // 36864 bytes
#define BTILE_B (128*LDK*4)            // 18432 bytes
#define STG_B   (ATILE_B + BTILE_B)    // 55296 bytes per stage
#define GEMM_SMEM_BYTES (3*STG_B)      // 165888

template<int EPI>
__device__ __forceinline__ void
gemm_body(const float* __restrict__ A, const float* __restrict__ W,
          const float* __restrict__ bias, const float* __restrict__ R,
          float* __restrict__ C, int N, int K, float* sm)
{
    const uint32_t sb = smem_u32(sm);

    const int tid  = threadIdx.x;
    const int wid  = tid >> 5;
    const int lane = tid & 31;
    const int wm   = wid & 3;        // m-warp (rows wm*64)
    const int wn   = wid >> 2;       // n-warp (cols wn*32)
    const int g    = lane >> 2;
    const int t    = lane & 3;
    const int mBase = blockIdx.y * 256;
    const int nBase = blockIdx.x * 128;

    const int r_ld  = tid >> 3;          // 0..63
    const int c4_ld = (tid & 7) << 2;    // 0..28

    auto load_stage = [&](int s, int c) {
        const uint32_t base = sb + (uint32_t)s * STG_B;
        const float* Ag = A + (size_t)mBase * K + c * BKC;
        const float* Wg = W + (size_t)nBase * K + c * BKC;
        #pragma unroll
        for (int i = 0; i < 4; i++) {    // A: 256 rows
            int r = r_ld + i * 64;
            cp16(base + (uint32_t)(r*LDK + c4_ld)*4, Ag + (size_t)r*K + c4_ld);
        }
        #pragma unroll
        for (int i = 0; i < 2; i++) {    // W: 128 rows
            int r = r_ld + i * 64;
            cp16(base + ATILE_B + (uint32_t)(r*LDK + c4_ld)*4, Wg + (size_t)r*K + c4_ld);
        }
    };

    const int nch = K / BKC;

    load_stage(0, 0); CP_COMMIT();
    load_stage(1, 1); CP_COMMIT();

    float acc[4][4][4];
    #pragma unroll
    for (int mf = 0; mf < 4; mf++)
        #pragma unroll
        for (int nf = 0; nf < 4; nf++)
            #pragma unroll
            for (int j = 0; j < 4; j++) acc[mf][nf][j] = 0.f;

    for (int c = 0; c < nch; c++) {
        CP_WAIT1();
        __syncthreads();

        int cn = c + 2;
        if (cn < nch) load_stage(cn % 3, cn);
        CP_COMMIT();

        const float* As = sm + (size_t)(c % 3) * (STG_B/4);
        const float* Bs = As + ATILE_B/4;

        #pragma unroll
        for (int k8 = 0; k8 < 4; k8++) {
            const int k0 = k8*8 + t;
            uint32_t a[4][4];
            #pragma unroll
            for (int mf = 0; mf < 4; mf++) {
                const float* AR = As + (wm*64 + mf*16 + g)*LDK;
                a[mf][0] = __float_as_uint(AR[k0]);
                a[mf][1] = __float_as_uint(AR[8*LDK + k0]);
                a[mf][2] = __float_as_uint(AR[k0 + 4]);
                a[mf][3] = __float_as_uint(AR[8*LDK + k0 + 4]);
            }
            #pragma unroll
            for (int nf = 0; nf < 4; nf++) {
                const float* BR = Bs + (wn*32 + nf*8 + g)*LDK + k0;
                uint32_t b0 = __float_as_uint(BR[0]);
                uint32_t b1 = __float_as_uint(BR[4]);
                #pragma unroll
                for (int mf = 0; mf < 4; mf++)
                    mma8(acc[mf][nf], a[mf][0], a[mf][1], a[mf][2], a[mf][3], b0, b1);
            }
        }
    }

    // ---- epilogue ----------------------------------------------------------
    #pragma unroll
    for (int nf = 0; nf < 4; nf++) {
        const int col = nBase + wn*32 + nf*8 + 2*t;
        const float b0 = bias[col], b1 = bias[col+1];
        #pragma unroll
        for (int mf = 0; mf < 4; mf++) {
            const int row = mBase + wm*64 + mf*16 + g;
            #pragma unroll
            for (int h = 0; h < 2; h++) {       // row, row+8
                size_t off = (size_t)(row + h*8) * N + col;
                float v0 = acc[mf][nf][h*2+0] + b0;
                float v1 = acc[mf][nf][h*2+1] + b1;
                if (EPI == EPI_GELU) {
                    v0 = 0.5f*v0*(1.0f + erff(v0*0.70710678118654752f));
                    v1 = 0.5f*v1*(1.0f + erff(v1*0.70710678118654752f));
                }
                if (EPI == EPI_RES) {
                    float2 rr = *(const float2*)&R[off];
                    v0 += rr.x; v1 += rr.y;
                }
                if (EPI == EPI_NONE) {   // QKV: pre-round to tf32 so flash's
                    v0 = f2tf32(v0);     // cp.async truncation is exact
                    v1 = f2tf32(v1);
                }
                *(float2*)&C[off] = make_float2(v0, v1);
            }
        }
    }
}

template<int EPI>
__global__ void __launch_bounds__(512, 1)
gemm_one(const float* __restrict__ A, const float* __restrict__ W,
         const float* __restrict__ bias, const float* __restrict__ R,
         float* __restrict__ C, int N, int K)
{
    extern __shared__ float sm[];
    gemm_body<EPI>(A, W, bias, R, C, N, K, sm);
}

// merged QKV: blockIdx.z selects weight/bias/output
__global__ void __launch_bounds__(512, 1)
gemm_qkv(const float* __restrict__ A,
         const float* __restrict__ wq, const float* __restrict__ bq, float* __restrict__ q,
         const float* __restrict__ wk, const float* __restrict__ bk, float* __restrict__ k,
         const float* __restrict__ wv, const float* __restrict__ bv, float* __restrict__ v)
{
    extern __shared__ float sm[];
    const float* W; const float* bias; float* C;
    if (blockIdx.z == 0)      { W = wq; bias = bq; C = q; }
    else if (blockIdx.z == 1) { W = wk; bias = bk; C = k; }
    else                      { W = wv; bias = bv; C = v; }
    gemm_body<EPI_NONE>(A, W, bias, nullptr, C, DIM, DIM, sm);
}

// ---------------- flash attention: mma.sync tf32, cp.async pipelined -------
#define FBM 64
#define FBN 64
#define QP 260
#define KP 260
#define VP 264
#define PST 68
#define FLASH_SMEM_BYTES ((64*QP + 64*KP + 64*VP + 64*PST + 256) * 4)  // 219136

__global__ void __launch_bounds__(256, 1)
flash_mma_kernel(const float* __restrict__ Q, const float* __restrict__ K,
                 const float* __restrict__ V, float* __restrict__ O)
{
    extern __shared__ float sm[];
    float* Qs   = sm;
    float* Ks   = Qs + 64*QP;
    float* Vs   = Ks + 64*KP;
    float* Ps   = Vs + 64*VP;
    float* pmax = Ps + 64*PST;
    float* psum = pmax + 128;

    const int qi  = gridDim.x - 1 - blockIdx.x;   // heavy tiles first
    const int b   = blockIdx.y;
    const int tid = threadIdx.x;
    const int wid = tid >> 5;
    const int lane = tid & 31;
    const int wm = wid & 3;
    const int wn = wid >> 2;
    const int g  = lane >> 2;
    const int t  = lane & 3;

    const uint32_t ks_u = smem_u32(Ks);
    const uint32_t vs_u = smem_u32(Vs);

    const float scale = 0.0625f;   // 1/sqrt(256), power of 2: preserves tf32
    const float* Qg = Q + ((size_t)b*TT + (size_t)qi*FBM) * DIM;
    const float* Kb = K + (size_t)b*TT*DIM;
    const float* Vb = V + (size_t)b*TT*DIM;

    auto cp_tile = [&](uint32_t dst_u, const float* src, int pad) {
        #pragma unroll
        for (int i = 0; i < 16; i++) {
            int f  = tid + i*256;
            int r  = f >> 6;
            int c4 = (f & 63) << 2;
            cp16(dst_u + (uint32_t)(r*pad + c4)*4, src + (size_t)r*DIM + c4);
        }
    };

    #pragma unroll
    for (int i = 0; i < 16; i++) {
        int f  = tid + i*256;
        int r  = f >> 6;
        int c4 = (f & 63) << 2;
        float4 qv = *(const float4*)(Qg + (size_t)r*DIM + c4);
        *(float4*)(Qs + r*QP + c4) = make_float4(
            qv.x*scale, qv.y*scale, qv.z*scale, qv.w*scale);
    }

    cp_tile(ks_u, Kb, KP); CP_COMMIT();            // K(0)
    cp_tile(vs_u, Vb, VP); CP_COMMIT();            // V(0)

    float o[16][4];
    #pragma unroll
    for (int i = 0; i < 16; i++)
        #pragma unroll
        for (int j = 0; j < 4; j++) o[i][j] = 0.f;
    float m0 = -1e30f, m1 = -1e30f, l0 = 0.f, l1 = 0.f;

    const int row0 = wm*16 + g;
    const float* QA = Qs + row0*QP;

    for (int kj = 0; kj <= qi; kj++) {
        if (kj > 0) {
            __syncthreads();                        // PV(kj-1) done: Vs free
            cp_tile(vs_u, Vb + (size_t)kj*FBN*DIM, VP); CP_COMMIT();  // V(kj)
        }
        CP_WAIT1();                                 // K(kj) arrived
        __syncthreads();

        // ---- S = Q K^T ----------------------------------------------------
        float s[4][4];
        #pragma unroll
        for (int nt = 0; nt < 4; nt++)
            #pragma unroll
            for (int j = 0; j < 4; j++) s[nt][j] = 0.f;

        #pragma unroll 4
        for (int k8 = 0; k8 < 32; k8++) {
            const int k0 = k8*8 + t;
            uint32_t a0 = __float_as_uint(QA[k0]);
            uint32_t a1 = __float_as_uint(QA[8*QP + k0]);
            uint32_t a2 = __float_as_uint(QA[k0 + 4]);
            uint32_t a3 = __float_as_uint(QA[8*QP + k0 + 4]);
            #pragma unroll
            for (int nt = 0; nt < 4; nt++) {
                const float* KB = Ks + (wn*32 + nt*8 + g)*KP + k0;
                uint32_t b0 = __float_as_uint(KB[0]);
                uint32_t b1 = __float_as_uint(KB[4]);
                mma8(s[nt], a0, a1, a2, a3, b0, b1);
            }
        }

        if (kj == qi) {   // causal mask on diagonal tile
            #pragma unroll
            for (int nt = 0; nt < 4; nt++) {
                int col = wn*32 + nt*8 + 2*t;
                if (col     > row0)     s[nt][0] = -1e30f;
                if (col + 1 > row0)     s[nt][1] = -1e30f;
                if (col     > row0 + 8) s[nt][2] = -1e30f;
                if (col + 1 > row0 + 8) s[nt][3] = -1e30f;
            }
        }

        // ---- online softmax ------------------------------------------------
        float pm0 = -1e30f, pm1 = -1e30f;
        #pragma unroll
        for (int nt = 0; nt < 4; nt++) {
            pm0 = fmaxf(pm0, fmaxf(s[nt][0], s[nt][1]));
            pm1 = fmaxf(pm1, fmaxf(s[nt][2], s[nt][3]));
        }
        pm0 = fmaxf(pm0, __shfl_xor_sync(0xffffffffu, pm0, 1));
        pm0 = fmaxf(pm0, __shfl_xor_sync(0xffffffffu, pm0, 2));
        pm1 = fmaxf(pm1, __shfl_xor_sync(0xffffffffu, pm1, 1));
        pm1 = fmaxf(pm1, __shfl_xor_sync(0xffffffffu, pm1, 2));
        if (t == 0) {
            pmax[wn*64 + row0]     = pm0;
            pmax[wn*64 + row0 + 8] = pm1;
        }
        __syncthreads();

        float nm0 = fmaxf(m0, fmaxf(pmax[row0],     pmax[64 + row0]));
        float nm1 = fmaxf(m1, fmaxf(pmax[row0 + 8], pmax[64 + row0 + 8]));
        float alpha0 = __expf(m0 - nm0);
        float alpha1 = __expf(m1 - nm1);
        m0 = nm0; m1 = nm1;

        float rs0 = 0.f, rs1 = 0.f;
        #pragma unroll
        for (int nt = 0; nt < 4; nt++) {
            s[nt][0] = __expf(s[nt][0] - nm0);
            s[nt][1] = __expf(s[nt][1] - nm0);
            s[nt][2] = __expf(s[nt][2] - nm1);
            s[nt][3] = __expf(s[nt][3] - nm1);
            rs0 += s[nt][0] + s[nt][1];
            rs1 += s[nt][2] + s[nt][3];
            int col = wn*32 + nt*8 + 2*t;
            *(float2*)(Ps + row0*PST + col) =
                make_float2(f2tf32(s[nt][0]), f2tf32(s[nt][1]));
            *(float2*)(Ps + (row0+8)*PST + col) =
                make_float2(f2tf32(s[nt][2]), f2tf32(s[nt][3]));
        }
        rs0 += __shfl_xor_sync(0xffffffffu, rs0, 1);
        rs0 += __shfl_xor_sync(0xffffffffu, rs0, 2);
        rs1 += __shfl_xor_sync(0xffffffffu, rs1, 1);
        rs1 += __shfl_xor_sync(0xffffffffu, rs1, 2);
        if (t == 0) {
            psum[wn*64 + row0]     = rs0;
            psum[wn*64 + row0 + 8] = rs1;
        }

        CP_WAIT0();                                 // V(kj) arrived
        __syncthreads();                            // + P/psum staged, Ks free

        if (kj < qi) {                              // prefetch K(kj+1) over PV
            cp_tile(ks_u, Kb + (size_t)(kj+1)*FBN*DIM, KP); CP_COMMIT();
        }

        l0 = l0*alpha0 + psum[row0]     + psum[64 + row0];
        l1 = l1*alpha1 + psum[row0 + 8] + psum[64 + row0 + 8];

        #pragma unroll
        for (int nt = 0; nt < 16; nt++) {
            o[nt][0] *= alpha0; o[nt][1] *= alpha0;
            o[nt][2] *= alpha1; o[nt][3] *= alpha1;
        }

        // ---- O += P V ------------------------------------------------------
        const float* PA = Ps + row0*PST;
        #pragma unroll
        for (int k8 = 0; k8 < 8; k8++) {
            const int k0 = k8*8 + t;
            uint32_t a0 = __float_as_uint(PA[k0]);
            uint32_t a1 = __float_as_uint(PA[8*PST + k0]);
            uint32_t a2 = __float_as_uint(PA[k0 + 4]);
            uint32_t a3 = __float_as_uint(PA[8*PST + k0 + 4]);
            #pragma unroll
            for (int nt = 0; nt < 16; nt++) {
                const int nb = wn*128 + nt*8 + g;
                uint32_t b0 = __float_as_uint(Vs[k0*VP + nb]);
                uint32_t b1 = __float_as_uint(Vs[(k0+4)*VP + nb]);
                mma8(o[nt], a0, a1, a2, a3, b0, b1);
            }
        }
    }

    float inv0 = 1.0f / l0;
    float inv1 = 1.0f / l1;
    float* Og = O + ((size_t)b*TT + (size_t)qi*FBM) * DIM;
    #pragma unroll
    for (int nt = 0; nt < 16; nt++) {
        int col = wn*128 + nt*8 + 2*t;
        *(float2*)(Og + (size_t)row0*DIM + col) =
            make_float2(o[nt][0]*inv0, o[nt][1]*inv0);
        *(float2*)(Og + (size_t)(row0+8)*DIM + col) =
            make_float2(o[nt][2]*inv1, o[nt][3]*inv1);
    }
}

// ---------------- launch ---------------------------------------------------
extern "C" void kernel_launch(void* const* d_in, const int* in_sizes, int n_in,
                              void* d_out, int out_size)
{
    const float* x           = (const float*)d_in[0];
    const float* attn_norm_w = (const float*)d_in[1];
    const float* mlp_norm_w  = (const float*)d_in[2];
    const float* wq = (const float*)d_in[3];  const float* bq = (const float*)d_in[4];
    const float* wk = (const float*)d_in[5];  const float* bk = (const float*)d_in[6];
    const float* wv = (const float*)d_in[7];  const float* bv = (const float*)d_in[8];
    const float* wo = (const float*)d_in[9];  const float* bo = (const float*)d_in[10];
    const float* w1 = (const float*)d_in[11]; const float* b1 = (const float*)d_in[12];
    const float* w2 = (const float*)d_in[13]; const float* b2 = (const float*)d_in[14];
    float* out = (float*)d_out;

    float *xn, *q, *k, *v, *attn, *x2, *hn, *h;
    cudaGetSymbolAddress((void**)&xn,   g_xn);
    cudaGetSymbolAddress((void**)&q,    g_q);
    cudaGetSymbolAddress((void**)&k,    g_k);
    cudaGetSymbolAddress((void**)&v,    g_v);
    cudaGetSymbolAddress((void**)&attn, g_attn);
    cudaGetSymbolAddress((void**)&x2,   g_x2);
    cudaGetSymbolAddress((void**)&hn,   g_hn);
    cudaGetSymbolAddress((void**)&h,    g_h);

    cudaFuncSetAttribute(flash_mma_kernel,
                         cudaFuncAttributeMaxDynamicSharedMemorySize, FLASH_SMEM_BYTES);
    cudaFuncSetAttribute(gemm_qkv,
                         cudaFuncAttributeMaxDynamicSharedMemorySize, GEMM_SMEM_BYTES);
    cudaFuncSetAttribute(gemm_one<EPI_RES>,
                         cudaFuncAttributeMaxDynamicSharedMemorySize, GEMM_SMEM_BYTES);
    cudaFuncSetAttribute(gemm_one<EPI_GELU>,
                         cudaFuncAttributeMaxDynamicSharedMemorySize, GEMM_SMEM_BYTES);

    // 1. attention-branch RMSNorm
    rmsnorm_kernel<<<ROWS, 256>>>(x, attn_norm_w, xn);

    // 2. QKV projections — one merged launch, z selects q/k/v
    gemm_qkv<<<dim3(DIM/128, ROWS/256, 3), 512, GEMM_SMEM_BYTES>>>(
        xn, wq, bq, q, wk, bk, k, wv, bv, v);

    // 3. causal attention (tensor cores, cp.async pipelined)
    flash_mma_kernel<<<dim3(TT/FBM, BB), 256, FLASH_SMEM_BYTES>>>(q, k, v, attn);

    // 4. output projection + residual
    gemm_one<EPI_RES><<<dim3(DIM/128, ROWS/256), 512, GEMM_SMEM_BYTES>>>(
        attn, wo, bo, x, x2, DIM, DIM);

    // 5. MLP-branch RMSNorm
    rmsnorm_kernel<<<ROWS, 256>>>(x2, mlp_norm_w, hn);

    // 6. MLP up + GELU
    gemm_one<EPI_GELU><<<dim3(4*DIM/128, ROWS/256), 512, GEMM_SMEM_BYTES>>>(
        hn, w1, b1, nullptr, h, 4*DIM, DIM);

    // 7. MLP down + residual -> out
    gemm_one<EPI_RES><<<dim3(DIM/128, ROWS/256), 512, GEMM_SMEM_BYTES>>>(
        h, w2, b2, x2, out, DIM, 4*DIM);
}